// round 4
// baseline (speedup 1.0000x reference)
#include <cuda_runtime.h>
#include <cstdint>

// Problem constants
#define BB 8
#define TT 4096
#define EE 2048
#define DD 128
#define M_TOTAL (BB*TT)            // 32768
#define NTILE 32                   // 128-row tiles per batch
#define NPAIR 528                  // NTILE*(NTILE+1)/2
#define SCALE 0.08838834764831845f // 128^-0.5

// Scratch (static __device__ arrays: allocation-free per harness rules)
__device__ unsigned g_q[M_TOTAL*DD];          // pre-rounded tf32 bits
__device__ unsigned g_k[M_TOTAL*DD];          // pre-rounded tf32 bits
__device__ float    g_v[M_TOTAL*DD];          // raw fp32
__device__ unsigned g_vp[M_TOTAL*DD];         // V'[s,d] = V[s,d]/colsum[s], tf32 bits
__device__ float    g_colsum[BB*TT];
__device__ unsigned g_p[(size_t)BB*NPAIR*128*128];  // exp(score) tiles, tf32 bits (~277MB)

// ---------------- helpers ----------------
// Round-to-nearest(ties away) to tf32: sign-magnitude fp32, add half-ulp of the
// 13-bit-truncated mantissa then mask. Equivalent to cvt.rna.tf32.f32.
__device__ __forceinline__ unsigned pre_tf(float f) {
    return (__float_as_uint(f) + 0x1000u) & 0xFFFFE000u;
}
__device__ __forceinline__ unsigned fixtf(unsigned u) {   // same, on raw fp32 bits
    return (u + 0x1000u) & 0xFFFFE000u;
}
__device__ __forceinline__ void cp16(void* smem_dst, const void* gptr) {
    unsigned s = (unsigned)__cvta_generic_to_shared(smem_dst);
    asm volatile("cp.async.cg.shared.global [%0], [%1], 16;\n" :: "r"(s), "l"(gptr));
}
__device__ __forceinline__ void cp_commit() {
    asm volatile("cp.async.commit_group;\n" ::: "memory");
}
__device__ __forceinline__ void mma_tf32(float c[4],
    unsigned a0, unsigned a1, unsigned a2, unsigned a3,
    unsigned b0, unsigned b1)
{
    asm volatile(
        "mma.sync.aligned.m16n8k8.row.col.f32.tf32.tf32.f32 "
        "{%0,%1,%2,%3}, {%4,%5,%6,%7}, {%8,%9}, {%0,%1,%2,%3};"
        : "+f"(c[0]), "+f"(c[1]), "+f"(c[2]), "+f"(c[3])
        : "r"(a0), "r"(a1), "r"(a2), "r"(a3), "r"(b0), "r"(b1));
}

// ---------------- kernel 0: zero colsum and output ----------------
__global__ void zero_kernel(float* __restrict__ out) {
    int i = blockIdx.x * 256 + threadIdx.x;          // grid covers 4,194,304
    out[i] = 0.0f;
    if (i < BB*TT) g_colsum[i] = 0.0f;
}

// ---------------- kernel 1: fused QKV projection ----------------
// grid (256, 3), 256 threads. Block computes 128(M) x 128(N), K=2048,
// double-buffered cp.async, 2 CTAs/SM.
#define QKV_SMEM ((2*4608 + 2*4352) * 4)   // xs[2][128*36] + ws[2][32*136]
__global__ __launch_bounds__(256, 2) void qkv_kernel(
    const float* __restrict__ x,
    const float* __restrict__ Wq,
    const float* __restrict__ Wk,
    const float* __restrict__ Wv)
{
    extern __shared__ unsigned sm[];
    unsigned* xs = sm;                // [2][128*36]
    unsigned* ws = sm + 2*4608;      // [2][32*136]

    const int tid = threadIdx.x;
    const int warp = tid >> 5, lane = tid & 31;
    const int gid = lane >> 2, t4 = lane & 3;
    const int warp_m = warp >> 1, warp_n = warp & 1;  // 4 x 2 warps
    const int m0 = blockIdx.x * 128;

    const float* W = (blockIdx.y == 0) ? Wq : (blockIdx.y == 1) ? Wk : Wv;

    float c[2][8][4] = {};

    auto prefetch = [&](int k0, int buf) {
        unsigned* xb = xs + buf*4608;
        unsigned* wb = ws + buf*4352;
        #pragma unroll
        for (int u = 0; u < 4; ++u) {
            int f = tid + u*256;
            int r = f >> 3, c4 = (f & 7) * 4;
            cp16(&xb[r*36 + c4], &x[(size_t)(m0 + r)*EE + k0 + c4]);
        }
        #pragma unroll
        for (int u = 0; u < 4; ++u) {
            int f = tid + u*256;
            int r = f >> 5, c4 = (f & 31) * 4;
            cp16(&wb[r*136 + c4], &W[(size_t)(k0 + r)*DD + c4]);
        }
        cp_commit();
    };

    prefetch(0, 0);
    for (int kc = 0; kc < 64; ++kc) {
        int buf = kc & 1;
        if (kc + 1 < 64) {
            prefetch((kc+1)*32, buf^1);
            asm volatile("cp.async.wait_group 1;\n" ::: "memory");
        } else {
            asm volatile("cp.async.wait_group 0;\n" ::: "memory");
        }
        __syncthreads();
        const unsigned* xb = xs + buf*4608;
        const unsigned* wb = ws + buf*4352;
        #pragma unroll
        for (int kk = 0; kk < 4; ++kk) {
            const int kb = kk*8 + t4;
            unsigned a[2][4];
            #pragma unroll
            for (int mt = 0; mt < 2; ++mt) {
                int rb = warp_m*32 + mt*16 + gid;
                a[mt][0] = fixtf(xb[rb*36 + kb]);
                a[mt][1] = fixtf(xb[(rb+8)*36 + kb]);
                a[mt][2] = fixtf(xb[rb*36 + kb + 4]);
                a[mt][3] = fixtf(xb[(rb+8)*36 + kb + 4]);
            }
            #pragma unroll
            for (int nt = 0; nt < 8; ++nt) {
                int n = warp_n*64 + nt*8 + gid;
                unsigned b0 = fixtf(wb[kb*136 + n]);
                unsigned b1 = fixtf(wb[(kb+4)*136 + n]);
                #pragma unroll
                for (int mt = 0; mt < 2; ++mt)
                    mma_tf32(c[mt][nt], a[mt][0],a[mt][1],a[mt][2],a[mt][3], b0, b1);
            }
        }
        __syncthreads();
    }

    const int yy = blockIdx.y;
    #pragma unroll
    for (int mt = 0; mt < 2; ++mt) {
        #pragma unroll
        for (int nt = 0; nt < 8; ++nt) {
            int row = m0 + warp_m*32 + mt*16 + gid;
            int col = warp_n*64 + nt*8 + 2*t4;
            size_t o0 = (size_t)row*DD + col;
            size_t o1 = (size_t)(row+8)*DD + col;
            if (yy == 0) {
                *(uint2*)&g_q[o0] = make_uint2(pre_tf(c[mt][nt][0]), pre_tf(c[mt][nt][1]));
                *(uint2*)&g_q[o1] = make_uint2(pre_tf(c[mt][nt][2]), pre_tf(c[mt][nt][3]));
            } else if (yy == 1) {
                *(uint2*)&g_k[o0] = make_uint2(pre_tf(c[mt][nt][0]), pre_tf(c[mt][nt][1]));
                *(uint2*)&g_k[o1] = make_uint2(pre_tf(c[mt][nt][2]), pre_tf(c[mt][nt][3]));
            } else {
                *(float2*)&g_v[o0] = make_float2(c[mt][nt][0], c[mt][nt][1]);
                *(float2*)&g_v[o1] = make_float2(c[mt][nt][2], c[mt][nt][3]);
            }
        }
    }
}

// ---------------- kernel 2: pass 1 — E = exp(QK^T*scale) masked; colsums; write E ----------------
// grid (528, B), 256 threads, double-buffered cp.async, 2 CTAs/SM.
#define P1_SMEM ((2*4608 + 2*4608) * 4)
__global__ __launch_bounds__(256, 2) void pass1_kernel()
{
    extern __shared__ unsigned sm[];
    unsigned* qs = sm;            // [2][128*36]
    unsigned* ks = sm + 2*4608;  // [2][128*36]
    __shared__ float colacc[128];

    const int bx = blockIdx.x;
    const int b  = blockIdx.y;
    int i = (int)((sqrtf(8.0f*bx + 1.0f) - 1.0f) * 0.5f);
    while ((i+1)*(i+2)/2 <= bx) ++i;
    while (i*(i+1)/2 > bx)      --i;
    const int j = bx - i*(i+1)/2;

    const int tid = threadIdx.x;
    const int warp = tid >> 5, lane = tid & 31;
    const int gid = lane >> 2, t4 = lane & 3;
    const int warp_m = warp >> 1, warp_n = warp & 1;

    if (tid < 128) colacc[tid] = 0.0f;

    const unsigned* qbase = g_q + ((size_t)b*TT + (size_t)i*128)*DD;
    const unsigned* kbase = g_k + ((size_t)b*TT + (size_t)j*128)*DD;

    auto prefetch = [&](int kc, int buf) {
        unsigned* qb = qs + buf*4608;
        unsigned* kb2 = ks + buf*4608;
        #pragma unroll
        for (int u = 0; u < 4; ++u) {
            int f = tid + u*256;
            int r = f >> 3, c4 = (f & 7) * 4;
            cp16(&qb[r*36 + c4],  qbase + (size_t)r*DD + kc*32 + c4);
            cp16(&kb2[r*36 + c4], kbase + (size_t)r*DD + kc*32 + c4);
        }
        cp_commit();
    };

    float c[2][8][4] = {};
    prefetch(0, 0);
    #pragma unroll
    for (int kc = 0; kc < 4; ++kc) {
        int buf = kc & 1;
        if (kc < 3) {
            prefetch(kc+1, buf^1);
            asm volatile("cp.async.wait_group 1;\n" ::: "memory");
        } else {
            asm volatile("cp.async.wait_group 0;\n" ::: "memory");
        }
        __syncthreads();
        const unsigned* qb = qs + buf*4608;
        const unsigned* kb2 = ks + buf*4608;
        #pragma unroll
        for (int kk = 0; kk < 4; ++kk) {
            const int kb = kk*8 + t4;
            unsigned a[2][4];
            #pragma unroll
            for (int mt = 0; mt < 2; ++mt) {
                int rb = warp_m*32 + mt*16 + gid;
                a[mt][0] = qb[rb*36 + kb];
                a[mt][1] = qb[(rb+8)*36 + kb];
                a[mt][2] = qb[rb*36 + kb + 4];
                a[mt][3] = qb[(rb+8)*36 + kb + 4];
            }
            #pragma unroll
            for (int nt = 0; nt < 8; ++nt) {
                int n = warp_n*64 + nt*8 + gid;
                unsigned b0 = kb2[n*36 + kb];
                unsigned b1 = kb2[n*36 + kb + 4];
                #pragma unroll
                for (int mt = 0; mt < 2; ++mt)
                    mma_tf32(c[mt][nt], a[mt][0],a[mt][1],a[mt][2],a[mt][3], b0, b1);
            }
        }
        __syncthreads();
    }

    const bool diag = (i == j);
    unsigned* ptile = g_p + ((size_t)b*NPAIR + (size_t)i*(i+1)/2 + j) * (128*128);
    #pragma unroll
    for (int nt = 0; nt < 8; ++nt) {
        int colA = warp_n*64 + nt*8 + 2*t4;
        float sA = 0.0f, sB = 0.0f;
        #pragma unroll
        for (int mt = 0; mt < 2; ++mt) {
            int r0 = warp_m*32 + mt*16 + gid;
            float e0 = __expf(c[mt][nt][0]*SCALE);
            float e1 = __expf(c[mt][nt][1]*SCALE);
            float e2 = __expf(c[mt][nt][2]*SCALE);
            float e3 = __expf(c[mt][nt][3]*SCALE);
            if (diag) {
                if (r0   < colA)   e0 = 0.0f;
                if (r0   < colA+1) e1 = 0.0f;
                if (r0+8 < colA)   e2 = 0.0f;
                if (r0+8 < colA+1) e3 = 0.0f;
            }
            sA += e0 + e2;
            sB += e1 + e3;
            *(uint2*)&ptile[r0*128 + colA]     = make_uint2(pre_tf(e0), pre_tf(e1));
            *(uint2*)&ptile[(r0+8)*128 + colA] = make_uint2(pre_tf(e2), pre_tf(e3));
        }
        atomicAdd(&colacc[colA],   sA);
        atomicAdd(&colacc[colA+1], sB);
    }
    __syncthreads();
    if (tid < 128)
        atomicAdd(&g_colsum[(size_t)b*TT + (size_t)j*128 + tid], colacc[tid]);
}

// ---------------- kernel 3: V'[s,d] = V[s,d] / colsum[s] ----------------
__global__ void vscale_kernel() {
    size_t idx = (size_t)blockIdx.x * 256 + threadIdx.x;   // 4,194,304 total
    float r = 1.0f / g_colsum[idx >> 7];
    g_vp[idx] = pre_tf(g_v[idx] * r);
}

// ---------------- kernel 4: pass 2 — out_i = sum_j P(i,j) @ V'(j) ----------------
// 384 blocks (i>=16 tiles split into 2 j-ranges, heavy first), 256 threads,
// double-buffered cp.async over a flat chunk stream, 2 CTAs/SM.
#define P2_SMEM ((2*4608 + 2*4352) * 4)   // pa[2][128*36] + pb[2][32*136]
__global__ __launch_bounds__(256, 2) void pass2_kernel(float* __restrict__ out)
{
    extern __shared__ unsigned sm[];
    unsigned* pa = sm;               // [2][128*36]  P chunk (t x 32s)
    unsigned* pb = sm + 2*4608;     // [2][32*136]  V' chunk (32s x d)

    const int bx = blockIdx.x;
    int b, i, jlo, jhi;
    if (bx < 128)       { b = bx & 7;        i = 31 - (bx >> 3);        jlo = 0;  jhi = 16;    }
    else if (bx < 256)  { int t = bx - 128;  b = t & 7; i = 31 - (t >> 3); jlo = 16; jhi = i + 1; }
    else                { int t = bx - 256;  b = t & 7; i = 15 - (t >> 3); jlo = 0;  jhi = i + 1; }
    const int NC = (jhi - jlo) * 4;

    const int tid = threadIdx.x;
    const int warp = tid >> 5, lane = tid & 31;
    const int gid = lane >> 2, t4 = lane & 3;
    const int warp_m = warp >> 1, warp_n = warp & 1;  // 4 x 2 warps

    const unsigned* pbase = g_p + ((size_t)b*NPAIR + (size_t)i*(i+1)/2) * (128*128);
    const unsigned* vbase = g_vp + (size_t)b*TT*DD;

    auto loadchunk = [&](int c, int buf) {
        int j = jlo + (c >> 2), kc = c & 3;
        const unsigned* pt = pbase + (size_t)j * (128*128);
        unsigned* A = pa + buf*4608;
        unsigned* Bv = pb + buf*4352;
        #pragma unroll
        for (int u = 0; u < 4; ++u) {
            int f = tid + u*256;
            int r = f >> 3, c4 = (f & 7) * 4;
            cp16(&A[r*36 + c4], pt + r*128 + kc*32 + c4);
        }
        #pragma unroll
        for (int u = 0; u < 4; ++u) {
            int f = tid + u*256;
            int r = f >> 5, c4 = (f & 31) * 4;
            cp16(&Bv[r*136 + c4], vbase + ((size_t)j*128 + kc*32 + r)*DD + c4);
        }
        cp_commit();
    };

    float o[2][8][4] = {};
    loadchunk(0, 0);
    for (int c = 0; c < NC; ++c) {
        int buf = c & 1;
        if (c + 1 < NC) {
            loadchunk(c+1, buf^1);
            asm volatile("cp.async.wait_group 1;\n" ::: "memory");
        } else {
            asm volatile("cp.async.wait_group 0;\n" ::: "memory");
        }
        __syncthreads();
        const unsigned* A = pa + buf*4608;
        const unsigned* Bv = pb + buf*4352;
        #pragma unroll
        for (int kk = 0; kk < 4; ++kk) {
            const int kb = kk*8 + t4;
            unsigned a[2][4];
            #pragma unroll
            for (int mt = 0; mt < 2; ++mt) {
                int rb = warp_m*32 + mt*16 + gid;
                a[mt][0] = A[rb*36 + kb];
                a[mt][1] = A[(rb+8)*36 + kb];
                a[mt][2] = A[rb*36 + kb + 4];
                a[mt][3] = A[(rb+8)*36 + kb + 4];
            }
            #pragma unroll
            for (int nt = 0; nt < 8; ++nt) {
                int n = warp_n*64 + nt*8 + gid;
                unsigned b0 = Bv[kb*136 + n];
                unsigned b1 = Bv[(kb+4)*136 + n];
                #pragma unroll
                for (int mt = 0; mt < 2; ++mt)
                    mma_tf32(o[mt][nt], a[mt][0],a[mt][1],a[mt][2],a[mt][3], b0, b1);
            }
        }
        __syncthreads();
    }

    // write / accumulate output tile
    float* obase = out + ((size_t)b*TT + (size_t)i*128)*DD;
    const bool partial = (i >= 16);   // split tiles: two blocks accumulate
    #pragma unroll
    for (int mt = 0; mt < 2; ++mt) {
        #pragma unroll
        for (int nt = 0; nt < 8; ++nt) {
            int r0 = warp_m*32 + mt*16 + gid;
            int col = warp_n*64 + nt*8 + 2*t4;
            float* p0 = &obase[(size_t)r0*DD + col];
            float* p1 = &obase[(size_t)(r0+8)*DD + col];
            if (partial) {
                atomicAdd(p0,   o[mt][nt][0]);
                atomicAdd(p0+1, o[mt][nt][1]);
                atomicAdd(p1,   o[mt][nt][2]);
                atomicAdd(p1+1, o[mt][nt][3]);
            } else {
                *(float2*)p0 = make_float2(o[mt][nt][0], o[mt][nt][1]);
                *(float2*)p1 = make_float2(o[mt][nt][2], o[mt][nt][3]);
            }
        }
    }
}

// ---------------- launch ----------------
extern "C" void kernel_launch(void* const* d_in, const int* in_sizes, int n_in,
                              void* d_out, int out_size)
{
    const float* x  = (const float*)d_in[0];
    const float* Wq = (const float*)d_in[1];
    const float* Wk = (const float*)d_in[2];
    const float* Wv = (const float*)d_in[3];
    float* out = (float*)d_out;

    cudaFuncSetAttribute(qkv_kernel,  cudaFuncAttributeMaxDynamicSharedMemorySize, QKV_SMEM);
    cudaFuncSetAttribute(pass1_kernel, cudaFuncAttributeMaxDynamicSharedMemorySize, P1_SMEM);
    cudaFuncSetAttribute(pass2_kernel, cudaFuncAttributeMaxDynamicSharedMemorySize, P2_SMEM);

    zero_kernel<<<16384, 256>>>(out);
    qkv_kernel<<<dim3(M_TOTAL/128, 3), 256, QKV_SMEM>>>(x, Wq, Wk, Wv);
    pass1_kernel<<<dim3(NPAIR, BB), 256, P1_SMEM>>>();
    vscale_kernel<<<16384, 256>>>();
    pass2_kernel<<<384, 256, P2_SMEM>>>(out);
}

// round 6
// speedup vs baseline: 1.0535x; 1.0535x over previous
#include <cuda_runtime.h>
#include <cstdint>

// Problem constants
#define BB 8
#define TT 4096
#define EE 2048
#define DD 128
#define M_TOTAL (BB*TT)            // 32768
#define NTILE 32
#define NPAIR 528                  // NTILE*(NTILE+1)/2
#define SCALE 0.08838834764831845f // 128^-0.5

// Scratch (static __device__ arrays: allocation-free per harness rules)
__device__ unsigned g_q[M_TOTAL*DD];          // pre-rounded tf32 bits, [t][d]
__device__ unsigned g_k[M_TOTAL*DD];          // pre-rounded tf32 bits, [s][d]
__device__ float    g_v[M_TOTAL*DD];          // raw fp32, [s][d]
__device__ unsigned g_vpt[M_TOTAL*DD];        // V'^T: [d][global_s], tf32 bits
__device__ float    g_colsum[BB*TT];
__device__ unsigned g_p[(size_t)BB*NPAIR*128*128];  // exp(score) tiles, tf32 bits
__device__ unsigned g_wt[3*DD*EE];            // W^T n-major [y][n][k], tf32 bits (3MB)

// ---------------- helpers ----------------
__device__ __forceinline__ unsigned pre_tf(float f) {
    return (__float_as_uint(f) + 0x1000u) & 0xFFFFE000u;
}
__device__ __forceinline__ unsigned fixtf(unsigned u) {
    return (u + 0x1000u) & 0xFFFFE000u;
}
__device__ __forceinline__ void cp16s(unsigned smem_dst, const void* gptr) {
    asm volatile("cp.async.cg.shared.global [%0], [%1], 16;\n" :: "r"(smem_dst), "l"(gptr));
}
__device__ __forceinline__ void cp_commit() {
    asm volatile("cp.async.commit_group;\n" ::: "memory");
}
__device__ __forceinline__ void mma_tf32(float c[4],
    unsigned a0, unsigned a1, unsigned a2, unsigned a3,
    unsigned b0, unsigned b1)
{
    asm volatile(
        "mma.sync.aligned.m16n8k8.row.col.f32.tf32.tf32.f32 "
        "{%0,%1,%2,%3}, {%4,%5,%6,%7}, {%8,%9}, {%0,%1,%2,%3};"
        : "+f"(c[0]), "+f"(c[1]), "+f"(c[2]), "+f"(c[3])
        : "r"(a0), "r"(a1), "r"(a2), "r"(a3), "r"(b0), "r"(b1));
}
__device__ __forceinline__ void ldsm4(unsigned& r0, unsigned& r1, unsigned& r2, unsigned& r3,
                                      uint32_t addr) {
    asm volatile("ldmatrix.sync.aligned.m8n8.x4.shared.b16 {%0,%1,%2,%3}, [%4];"
        : "=r"(r0), "=r"(r1), "=r"(r2), "=r"(r3) : "r"(addr));
}

// ---- shared GEMM skeleton constants ----
// Tile: A [128 rows][36 words], B [128 rows][36 words] per stage; 3 stages.
#define TILE_WORDS 4608               // 128*36
#define B_OFF_BYTES 18432             // TILE_WORDS*4
#define STAGE_BYTES 36864             // 2 tiles
#define GEMM_SMEM (3*STAGE_BYTES)     // 110592

// Load one 128x32 A tile + 128x32 B tile (16B cp.async), 256 threads.
__device__ __forceinline__ void load_tiles(uint32_t st, int tid,
    const unsigned* gA, size_t sA, const unsigned* gB, size_t sB)
{
    #pragma unroll
    for (int u = 0; u < 4; ++u) {
        int f = tid + u*256; int r = f >> 3; int c4 = (f & 7) * 4;
        cp16s(st + (unsigned)(r*36 + c4)*4, gA + (size_t)r*sA + c4);
    }
    #pragma unroll
    for (int u = 0; u < 4; ++u) {
        int f = tid + u*256; int r = f >> 3; int c4 = (f & 7) * 4;
        cp16s(st + B_OFF_BYTES + (unsigned)(r*36 + c4)*4, gB + (size_t)r*sB + c4);
    }
    cp_commit();
}

// One 32-k chunk of MMAs for a 32m x 64n warp tile via ldmatrix fragments.
template<bool FIX>
__device__ __forceinline__ void gemm_chunk(uint32_t a_base, uint32_t b_base,
                                           float (&acc)[2][8][4])
{
    #pragma unroll
    for (int kk = 0; kk < 4; ++kk) {
        unsigned a0[4], a1[4];
        ldsm4(a0[0], a0[1], a0[2], a0[3], a_base + kk*32);
        ldsm4(a1[0], a1[1], a1[2], a1[3], a_base + kk*32 + 2304);
        if (FIX) {
            #pragma unroll
            for (int q = 0; q < 4; ++q) { a0[q] = fixtf(a0[q]); a1[q] = fixtf(a1[q]); }
        }
        #pragma unroll
        for (int p = 0; p < 4; ++p) {
            unsigned b[4];
            ldsm4(b[0], b[1], b[2], b[3], b_base + kk*32 + p*2304);
            mma_tf32(acc[0][2*p],   a0[0], a0[1], a0[2], a0[3], b[0], b[1]);
            mma_tf32(acc[0][2*p+1], a0[0], a0[1], a0[2], a0[3], b[2], b[3]);
            mma_tf32(acc[1][2*p],   a1[0], a1[1], a1[2], a1[3], b[0], b[1]);
            mma_tf32(acc[1][2*p+1], a1[0], a1[1], a1[2], a1[3], b[2], b[3]);
        }
    }
}

// Per-lane ldmatrix base offsets (bytes, relative to stage start).
__device__ __forceinline__ uint32_t a_lane_off(int warp_m, int lane) {
    int row = warp_m*32 + ((lane >> 3) & 1)*8 + (lane & 7);
    int col = (lane >> 4) * 4;
    return (uint32_t)(row*36 + col) * 4;
}
__device__ __forceinline__ uint32_t b_lane_off(int warp_n, int lane) {
    int row = warp_n*64 + (lane >> 4)*8 + (lane & 7);
    int col = ((lane >> 3) & 1) * 4;
    return B_OFF_BYTES + (uint32_t)(row*36 + col) * 4;
}

// ---------------- kernel 0: zero colsum and output ----------------
__global__ void zero_kernel(float* __restrict__ out) {
    int i = blockIdx.x * 256 + threadIdx.x;
    out[i] = 0.0f;
    if (i < BB*TT) g_colsum[i] = 0.0f;
}

// ---------------- kernel W: W^T n-major, tf32 pre-rounded ----------------
// grid (64, 3), 256 threads. Block: 32 k-rows x 128 n. g_wt[(y*128+n)*2048 + k].
__global__ __launch_bounds__(256) void wtrans_kernel(
    const float* __restrict__ Wq, const float* __restrict__ Wk, const float* __restrict__ Wv)
{
    __shared__ float ws[32*129];
    const int kc = blockIdx.x, y = blockIdx.y;
    const float* W = (y == 0) ? Wq : (y == 1) ? Wk : Wv;
    const int tid = threadIdx.x;
    #pragma unroll
    for (int u = 0; u < 16; ++u) {
        int f = tid + u*256;               // 0..4095
        int r = f >> 7, n = f & 127;
        ws[r*129 + n] = W[(size_t)(kc*32 + r)*DD + n];
    }
    __syncthreads();
    #pragma unroll
    for (int u = 0; u < 4; ++u) {
        int n = (tid >> 3) + u*32;
        int kq = (tid & 7) * 4;
        uint4 v;
        v.x = pre_tf(ws[(kq+0)*129 + n]);
        v.y = pre_tf(ws[(kq+1)*129 + n]);
        v.z = pre_tf(ws[(kq+2)*129 + n]);
        v.w = pre_tf(ws[(kq+3)*129 + n]);
        *(uint4*)&g_wt[((size_t)y*DD + n)*EE + kc*32 + kq] = v;
    }
}

// ---------------- kernel 1: QKV projection ----------------
// grid 768 (m-tile major, y fastest: bid = m*3+y so siblings share x via L2).
__global__ __launch_bounds__(256, 2) void qkv_kernel(const float* __restrict__ x)
{
    extern __shared__ unsigned sm[];
    const uint32_t base32 = (uint32_t)__cvta_generic_to_shared(sm);

    const int tid = threadIdx.x;
    const int warp = tid >> 5, lane = tid & 31;
    const int gid = lane >> 2, t4 = lane & 3;
    const int warp_m = warp >> 1, warp_n = warp & 1;
    const int bid = blockIdx.x;
    const int m0 = (bid / 3) * 128;
    const int y  = bid % 3;

    const unsigned* gA0 = (const unsigned*)x + (size_t)m0*EE;
    const unsigned* gB0 = g_wt + (size_t)y*DD*EE;

    const uint32_t aoff = a_lane_off(warp_m, lane);
    const uint32_t boff = b_lane_off(warp_n, lane);

    float acc[2][8][4] = {};

    load_tiles(base32,               tid, gA0,      EE, gB0,      EE);
    load_tiles(base32 + STAGE_BYTES, tid, gA0 + 32, EE, gB0 + 32, EE);

    for (int c = 0; c < 64; ++c) {
        if (c + 1 < 64) asm volatile("cp.async.wait_group 1;\n" ::: "memory");
        else            asm volatile("cp.async.wait_group 0;\n" ::: "memory");
        __syncthreads();
        if (c + 2 < 64)
            load_tiles(base32 + ((c+2)%3)*STAGE_BYTES, tid,
                       gA0 + (c+2)*32, EE, gB0 + (c+2)*32, EE);
        uint32_t st = base32 + (c%3)*STAGE_BYTES;
        gemm_chunk<true>(st + aoff, st + boff, acc);   // FIX: x is raw fp32
    }

    #pragma unroll
    for (int mt = 0; mt < 2; ++mt) {
        #pragma unroll
        for (int nt = 0; nt < 8; ++nt) {
            int row = m0 + warp_m*32 + mt*16 + gid;
            int col = warp_n*64 + nt*8 + 2*t4;
            size_t o0 = (size_t)row*DD + col;
            size_t o1 = (size_t)(row+8)*DD + col;
            if (y == 0) {
                *(uint2*)&g_q[o0] = make_uint2(pre_tf(acc[mt][nt][0]), pre_tf(acc[mt][nt][1]));
                *(uint2*)&g_q[o1] = make_uint2(pre_tf(acc[mt][nt][2]), pre_tf(acc[mt][nt][3]));
            } else if (y == 1) {
                *(uint2*)&g_k[o0] = make_uint2(pre_tf(acc[mt][nt][0]), pre_tf(acc[mt][nt][1]));
                *(uint2*)&g_k[o1] = make_uint2(pre_tf(acc[mt][nt][2]), pre_tf(acc[mt][nt][3]));
            } else {
                *(float2*)&g_v[o0] = make_float2(acc[mt][nt][0], acc[mt][nt][1]);
                *(float2*)&g_v[o1] = make_float2(acc[mt][nt][2], acc[mt][nt][3]);
            }
        }
    }
}

// ---------------- kernel 2: pass 1 — E = exp(QK^T*scale); colsums; store E ----------------
__global__ __launch_bounds__(256, 2) void pass1_kernel()
{
    extern __shared__ unsigned sm[];
    const uint32_t base32 = (uint32_t)__cvta_generic_to_shared(sm);
    __shared__ float colacc[128];

    const int bx = blockIdx.x;
    const int b  = blockIdx.y;
    int i = (int)((sqrtf(8.0f*bx + 1.0f) - 1.0f) * 0.5f);
    while ((i+1)*(i+2)/2 <= bx) ++i;
    while (i*(i+1)/2 > bx)      --i;
    const int j = bx - i*(i+1)/2;

    const int tid = threadIdx.x;
    const int warp = tid >> 5, lane = tid & 31;
    const int gid = lane >> 2, t4 = lane & 3;
    const int warp_m = warp >> 1, warp_n = warp & 1;

    if (tid < 128) colacc[tid] = 0.0f;

    const unsigned* gA0 = g_q + ((size_t)b*TT + (size_t)i*128)*DD;
    const unsigned* gB0 = g_k + ((size_t)b*TT + (size_t)j*128)*DD;

    const uint32_t aoff = a_lane_off(warp_m, lane);
    const uint32_t boff = b_lane_off(warp_n, lane);

    float acc[2][8][4] = {};

    load_tiles(base32,               tid, gA0,      DD, gB0,      DD);
    load_tiles(base32 + STAGE_BYTES, tid, gA0 + 32, DD, gB0 + 32, DD);

    #pragma unroll
    for (int c = 0; c < 4; ++c) {
        if (c < 3) asm volatile("cp.async.wait_group 1;\n" ::: "memory");
        else       asm volatile("cp.async.wait_group 0;\n" ::: "memory");
        __syncthreads();
        if (c + 2 < 4)
            load_tiles(base32 + ((c+2)%3)*STAGE_BYTES, tid,
                       gA0 + (c+2)*32, DD, gB0 + (c+2)*32, DD);
        uint32_t st = base32 + (c%3)*STAGE_BYTES;
        gemm_chunk<false>(st + aoff, st + boff, acc);
    }

    const bool diag = (i == j);
    unsigned* ptile = g_p + ((size_t)b*NPAIR + (size_t)i*(i+1)/2 + j) * (128*128);
    #pragma unroll
    for (int nt = 0; nt < 8; ++nt) {
        int colA = warp_n*64 + nt*8 + 2*t4;
        float sA = 0.0f, sB = 0.0f;
        #pragma unroll
        for (int mt = 0; mt < 2; ++mt) {
            int r0 = warp_m*32 + mt*16 + gid;
            float e0 = __expf(acc[mt][nt][0]*SCALE);
            float e1 = __expf(acc[mt][nt][1]*SCALE);
            float e2 = __expf(acc[mt][nt][2]*SCALE);
            float e3 = __expf(acc[mt][nt][3]*SCALE);
            if (diag) {
                if (r0   < colA)   e0 = 0.0f;
                if (r0   < colA+1) e1 = 0.0f;
                if (r0+8 < colA)   e2 = 0.0f;
                if (r0+8 < colA+1) e3 = 0.0f;
            }
            sA += e0 + e2;
            sB += e1 + e3;
            *(uint2*)&ptile[r0*128 + colA]     = make_uint2(pre_tf(e0), pre_tf(e1));
            *(uint2*)&ptile[(r0+8)*128 + colA] = make_uint2(pre_tf(e2), pre_tf(e3));
        }
        atomicAdd(&colacc[colA],   sA);
        atomicAdd(&colacc[colA+1], sB);
    }
    __syncthreads();
    if (tid < 128)
        atomicAdd(&g_colsum[(size_t)b*TT + (size_t)j*128 + tid], colacc[tid]);
}

// ---------------- kernel 3: V'^T[d][s] = V[s][d]/colsum[s], tf32, transposed ----------------
__global__ void vscale_t_kernel() {
    __shared__ float ts[32][33];
    const int s0 = blockIdx.x * 32, d0 = blockIdx.y * 32;
    const int tx = threadIdx.x, ty = threadIdx.y;
    #pragma unroll
    for (int q = 0; q < 4; ++q) {
        int s = s0 + ty + q*8;
        float r = 1.0f / g_colsum[s];
        ts[ty + q*8][tx] = g_v[(size_t)s*DD + d0 + tx] * r;
    }
    __syncthreads();
    #pragma unroll
    for (int q = 0; q < 4; ++q) {
        int d = d0 + ty + q*8;
        g_vpt[(size_t)d*M_TOTAL + s0 + tx] = pre_tf(ts[tx][ty + q*8]);
    }
}

// ---------------- kernel 4: pass 2 — out_i = sum_j P(i,j) @ V'(j) ----------------
__global__ __launch_bounds__(256, 2) void pass2_kernel(float* __restrict__ out)
{
    extern __shared__ unsigned sm[];
    const uint32_t base32 = (uint32_t)__cvta_generic_to_shared(sm);

    const int bx = blockIdx.x;
    int b, i, jlo, jhi;
    if (bx < 128)       { b = bx & 7;        i = 31 - (bx >> 3);        jlo = 0;  jhi = 16;    }
    else if (bx < 256)  { int t = bx - 128;  b = t & 7; i = 31 - (t >> 3); jlo = 16; jhi = i + 1; }
    else                { int t = bx - 256;  b = t & 7; i = 15 - (t >> 3); jlo = 0;  jhi = i + 1; }
    const int NC = (jhi - jlo) * 4;

    const int tid = threadIdx.x;
    const int warp = tid >> 5, lane = tid & 31;
    const int gid = lane >> 2, t4 = lane & 3;
    const int warp_m = warp >> 1, warp_n = warp & 1;

    const unsigned* pbase = g_p + ((size_t)b*NPAIR + (size_t)i*(i+1)/2) * (128*128);
    const unsigned* vbase = g_vpt + (size_t)b*TT;      // row d stride = M_TOTAL

    const uint32_t aoff = a_lane_off(warp_m, lane);
    const uint32_t boff = b_lane_off(warp_n, lane);

    auto loadc = [&](int cc, int s) {
        int j = jlo + (cc >> 2), kc = cc & 3;
        load_tiles(base32 + s*STAGE_BYTES, tid,
                   pbase + (size_t)j*(128*128) + kc*32, 128,
                   vbase + (size_t)j*128 + kc*32, (size_t)M_TOTAL);
    };

    float acc[2][8][4] = {};

    loadc(0, 0);
    loadc(1, 1);
    for (int c = 0; c < NC; ++c) {
        if (c + 1 < NC) asm volatile("cp.async.wait_group 1;\n" ::: "memory");
        else            asm volatile("cp.async.wait_group 0;\n" ::: "memory");
        __syncthreads();
        if (c + 2 < NC) loadc(c + 2, (c+2)%3);
        uint32_t st = base32 + (c%3)*STAGE_BYTES;
        gemm_chunk<false>(st + aoff, st + boff, acc);
    }

    float* obase = out + ((size_t)b*TT + (size_t)i*128)*DD;
    const bool partial = (i >= 16);
    #pragma unroll
    for (int mt = 0; mt < 2; ++mt) {
        #pragma unroll
        for (int nt = 0; nt < 8; ++nt) {
            int r0 = warp_m*32 + mt*16 + gid;
            int col = warp_n*64 + nt*8 + 2*t4;
            float* p0 = &obase[(size_t)r0*DD + col];
            float* p1 = &obase[(size_t)(r0+8)*DD + col];
            if (partial) {
                atomicAdd(p0,   acc[mt][nt][0]);
                atomicAdd(p0+1, acc[mt][nt][1]);
                atomicAdd(p1,   acc[mt][nt][2]);
                atomicAdd(p1+1, acc[mt][nt][3]);
            } else {
                *(float2*)p0 = make_float2(acc[mt][nt][0], acc[mt][nt][1]);
                *(float2*)p1 = make_float2(acc[mt][nt][2], acc[mt][nt][3]);
            }
        }
    }
}

// ---------------- launch ----------------
extern "C" void kernel_launch(void* const* d_in, const int* in_sizes, int n_in,
                              void* d_out, int out_size)
{
    const float* x  = (const float*)d_in[0];
    const float* Wq = (const float*)d_in[1];
    const float* Wk = (const float*)d_in[2];
    const float* Wv = (const float*)d_in[3];
    float* out = (float*)d_out;

    cudaFuncSetAttribute(qkv_kernel,   cudaFuncAttributeMaxDynamicSharedMemorySize, GEMM_SMEM);
    cudaFuncSetAttribute(pass1_kernel, cudaFuncAttributeMaxDynamicSharedMemorySize, GEMM_SMEM);
    cudaFuncSetAttribute(pass2_kernel, cudaFuncAttributeMaxDynamicSharedMemorySize, GEMM_SMEM);

    zero_kernel<<<16384, 256>>>(out);
    wtrans_kernel<<<dim3(64, 3), 256>>>(Wq, Wk, Wv);
    qkv_kernel<<<768, 256, GEMM_SMEM>>>(x);
    pass1_kernel<<<dim3(NPAIR, BB), 256, GEMM_SMEM>>>();
    vscale_t_kernel<<<dim3(M_TOTAL/32, DD/32), dim3(32, 8)>>>();
    pass2_kernel<<<384, 256, GEMM_SMEM>>>(out);
}

// round 7
// speedup vs baseline: 1.2268x; 1.1644x over previous
#include <cuda_runtime.h>
#include <cstdint>

// Problem constants
#define BB 8
#define TT 4096
#define EE 2048
#define DD 128
#define M_TOTAL (BB*TT)            // 32768
#define NTILE 32
#define NPAIR 528                  // NTILE*(NTILE+1)/2
#define SCALE 0.08838834764831845f // 128^-0.5

// Scratch (static __device__ arrays: allocation-free per harness rules)
__device__ unsigned g_q[M_TOTAL*DD];          // pre-rounded tf32 bits, [t][d]
__device__ unsigned g_k[M_TOTAL*DD];          // pre-rounded tf32 bits, [s][d]
__device__ float    g_v[M_TOTAL*DD];          // raw fp32, [s][d]
__device__ unsigned g_vpt[M_TOTAL*DD];        // V'^T: [d][global_s], tf32 bits
__device__ float    g_colsum[BB*TT];
__device__ unsigned g_p[(size_t)BB*NPAIR*128*128];  // exp(score) tiles, tf32 bits
__device__ unsigned g_wt[3*DD*EE];            // W^T n-major [y][n][k], tf32 bits (3MB)

// ---------------- helpers ----------------
__device__ __forceinline__ unsigned pre_tf(float f) {
    return (__float_as_uint(f) + 0x1000u) & 0xFFFFE000u;
}
__device__ __forceinline__ unsigned fixtf(unsigned u) {
    return (u + 0x1000u) & 0xFFFFE000u;
}
__device__ __forceinline__ void cp16s(unsigned smem_dst, const void* gptr) {
    asm volatile("cp.async.cg.shared.global [%0], [%1], 16;\n" :: "r"(smem_dst), "l"(gptr));
}
__device__ __forceinline__ void cp_commit() {
    asm volatile("cp.async.commit_group;\n" ::: "memory");
}
__device__ __forceinline__ void mma_tf32(float c[4],
    unsigned a0, unsigned a1, unsigned a2, unsigned a3,
    unsigned b0, unsigned b1)
{
    asm volatile(
        "mma.sync.aligned.m16n8k8.row.col.f32.tf32.tf32.f32 "
        "{%0,%1,%2,%3}, {%4,%5,%6,%7}, {%8,%9}, {%0,%1,%2,%3};"
        : "+f"(c[0]), "+f"(c[1]), "+f"(c[2]), "+f"(c[3])
        : "r"(a0), "r"(a1), "r"(a2), "r"(a3), "r"(b0), "r"(b1));
}
__device__ __forceinline__ void ldsm4(unsigned& r0, unsigned& r1, unsigned& r2, unsigned& r3,
                                      uint32_t addr) {
    asm volatile("ldmatrix.sync.aligned.m8n8.x4.shared.b16 {%0,%1,%2,%3}, [%4];"
        : "=r"(r0), "=r"(r1), "=r"(r2), "=r"(r3) : "r"(addr));
}

// ---- shared GEMM skeleton constants (A[128][36] + B[128][36] per stage) ----
#define TILE_WORDS 4608               // 128*36
#define B_OFF_BYTES 18432
#define STAGE_BYTES 36864
#define GEMM_SMEM (3*STAGE_BYTES)     // 110592

__device__ __forceinline__ void load_tiles(uint32_t st, int tid,
    const unsigned* gA, size_t sA, const unsigned* gB, size_t sB)
{
    #pragma unroll
    for (int u = 0; u < 4; ++u) {
        int f = tid + u*256; int r = f >> 3; int c4 = (f & 7) * 4;
        cp16s(st + (unsigned)(r*36 + c4)*4, gA + (size_t)r*sA + c4);
    }
    #pragma unroll
    for (int u = 0; u < 4; ++u) {
        int f = tid + u*256; int r = f >> 3; int c4 = (f & 7) * 4;
        cp16s(st + B_OFF_BYTES + (unsigned)(r*36 + c4)*4, gB + (size_t)r*sB + c4);
    }
    cp_commit();
}

// 32-k chunk of MMAs, 32m x 64n warp tile; B row stride selectable.
template<bool FIX, int BSTRIDE_W>
__device__ __forceinline__ void gemm_chunk(uint32_t a_base, uint32_t b_base,
                                           float (&acc)[2][8][4])
{
    const int PSTEP = 16*BSTRIDE_W*4;
    #pragma unroll
    for (int kk = 0; kk < 4; ++kk) {
        unsigned a0[4], a1[4];
        ldsm4(a0[0], a0[1], a0[2], a0[3], a_base + kk*32);
        ldsm4(a1[0], a1[1], a1[2], a1[3], a_base + kk*32 + 2304);
        if (FIX) {
            #pragma unroll
            for (int q = 0; q < 4; ++q) { a0[q] = fixtf(a0[q]); a1[q] = fixtf(a1[q]); }
        }
        #pragma unroll
        for (int p = 0; p < 4; ++p) {
            unsigned b[4];
            ldsm4(b[0], b[1], b[2], b[3], b_base + kk*32 + p*PSTEP);
            mma_tf32(acc[0][2*p],   a0[0], a0[1], a0[2], a0[3], b[0], b[1]);
            mma_tf32(acc[0][2*p+1], a0[0], a0[1], a0[2], a0[3], b[2], b[3]);
            mma_tf32(acc[1][2*p],   a1[0], a1[1], a1[2], a1[3], b[0], b[1]);
            mma_tf32(acc[1][2*p+1], a1[0], a1[1], a1[2], a1[3], b[2], b[3]);
        }
    }
}

__device__ __forceinline__ uint32_t a_lane_off(int warp_m, int lane) {
    int row = warp_m*32 + ((lane >> 3) & 1)*8 + (lane & 7);
    int col = (lane >> 4) * 4;
    return (uint32_t)(row*36 + col) * 4;
}
template<int BSTRIDE_W>
__device__ __forceinline__ uint32_t b_lane_off(int warp_n, int lane) {
    int row = warp_n*64 + (lane >> 4)*8 + (lane & 7);
    int col = ((lane >> 3) & 1) * 4;
    return (uint32_t)(row*BSTRIDE_W + col) * 4;
}

// ---------------- kernel 0: zero colsum and output ----------------
__global__ void zero_kernel(float* __restrict__ out) {
    int i = blockIdx.x * 256 + threadIdx.x;
    out[i] = 0.0f;
    if (i < BB*TT) g_colsum[i] = 0.0f;
}

// ---------------- kernel W: W^T n-major, tf32 pre-rounded ----------------
__global__ __launch_bounds__(256) void wtrans_kernel(
    const float* __restrict__ Wq, const float* __restrict__ Wk, const float* __restrict__ Wv)
{
    __shared__ float ws[32*129];
    const int kc = blockIdx.x, y = blockIdx.y;
    const float* W = (y == 0) ? Wq : (y == 1) ? Wk : Wv;
    const int tid = threadIdx.x;
    #pragma unroll
    for (int u = 0; u < 16; ++u) {
        int f = tid + u*256;
        int r = f >> 7, n = f & 127;
        ws[r*129 + n] = W[(size_t)(kc*32 + r)*DD + n];
    }
    __syncthreads();
    #pragma unroll
    for (int u = 0; u < 4; ++u) {
        int n = (tid >> 3) + u*32;
        int kq = (tid & 7) * 4;
        uint4 v;
        v.x = pre_tf(ws[(kq+0)*129 + n]);
        v.y = pre_tf(ws[(kq+1)*129 + n]);
        v.z = pre_tf(ws[(kq+2)*129 + n]);
        v.w = pre_tf(ws[(kq+3)*129 + n]);
        *(uint4*)&g_wt[((size_t)y*DD + n)*EE + kc*32 + kq] = v;
    }
}

// ---------------- kernel 1: QKV projection ----------------
__global__ __launch_bounds__(256, 2) void qkv_kernel(const float* __restrict__ x)
{
    extern __shared__ unsigned sm[];
    const uint32_t base32 = (uint32_t)__cvta_generic_to_shared(sm);

    const int tid = threadIdx.x;
    const int warp = tid >> 5, lane = tid & 31;
    const int gid = lane >> 2, t4 = lane & 3;
    const int warp_m = warp >> 1, warp_n = warp & 1;
    const int bid = blockIdx.x;
    const int m0 = (bid / 3) * 128;
    const int y  = bid % 3;

    const unsigned* gA0 = (const unsigned*)x + (size_t)m0*EE;
    const unsigned* gB0 = g_wt + (size_t)y*DD*EE;

    const uint32_t aoff = a_lane_off(warp_m, lane);
    const uint32_t boff = B_OFF_BYTES + b_lane_off<36>(warp_n, lane);

    float acc[2][8][4] = {};

    load_tiles(base32,               tid, gA0,      EE, gB0,      EE);
    load_tiles(base32 + STAGE_BYTES, tid, gA0 + 32, EE, gB0 + 32, EE);

    for (int c = 0; c < 64; ++c) {
        if (c + 1 < 64) asm volatile("cp.async.wait_group 1;\n" ::: "memory");
        else            asm volatile("cp.async.wait_group 0;\n" ::: "memory");
        __syncthreads();
        if (c + 2 < 64)
            load_tiles(base32 + ((c+2)%3)*STAGE_BYTES, tid,
                       gA0 + (c+2)*32, EE, gB0 + (c+2)*32, EE);
        uint32_t st = base32 + (c%3)*STAGE_BYTES;
        gemm_chunk<true, 36>(st + aoff, st + boff, acc);
    }

    #pragma unroll
    for (int mt = 0; mt < 2; ++mt) {
        #pragma unroll
        for (int nt = 0; nt < 8; ++nt) {
            int row = m0 + warp_m*32 + mt*16 + gid;
            int col = warp_n*64 + nt*8 + 2*t4;
            size_t o0 = (size_t)row*DD + col;
            size_t o1 = (size_t)(row+8)*DD + col;
            if (y == 0) {
                *(uint2*)&g_q[o0] = make_uint2(pre_tf(acc[mt][nt][0]), pre_tf(acc[mt][nt][1]));
                *(uint2*)&g_q[o1] = make_uint2(pre_tf(acc[mt][nt][2]), pre_tf(acc[mt][nt][3]));
            } else if (y == 1) {
                *(uint2*)&g_k[o0] = make_uint2(pre_tf(acc[mt][nt][0]), pre_tf(acc[mt][nt][1]));
                *(uint2*)&g_k[o1] = make_uint2(pre_tf(acc[mt][nt][2]), pre_tf(acc[mt][nt][3]));
            } else {
                *(float2*)&g_v[o0] = make_float2(acc[mt][nt][0], acc[mt][nt][1]);
                *(float2*)&g_v[o1] = make_float2(acc[mt][nt][2], acc[mt][nt][3]);
            }
        }
    }
}

// ---------------- kernel 2: pass 1 v2 — resident k-tile, streamed q-tiles ----------------
// grid (144, 8). Block = (b, j, mc): k-tile j resident in smem; q-tiles i0..i0+nt-1 stream.
// smem: B[128][132] (67584B) + A[2][128][36] (36864B) = 104448B -> 2 CTAs/SM.
#define P1V2_BWORDS (128*132)
#define P1V2_SMEM   ((P1V2_BWORDS + 2*TILE_WORDS) * 4)
__global__ __launch_bounds__(256, 2) void pass1_kernel()
{
    extern __shared__ unsigned sm[];
    const uint32_t base32 = (uint32_t)__cvta_generic_to_shared(sm);
    const uint32_t aStage = base32 + P1V2_BWORDS*4;
    __shared__ float colacc[128];

    const int b = blockIdx.y;
    int rem = blockIdx.x, j = 0, mc = 0;
    #pragma unroll 1
    for (j = 0; j < 32; ++j) {
        int c = (32 - j + 3) >> 2;
        if (rem < c) { mc = rem; break; }
        rem -= c;
    }
    const int i0 = j + mc*4;
    const int ntl = (32 - i0 < 4) ? (32 - i0) : 4;
    const int NCH = ntl * 4;

    const int tid = threadIdx.x;
    const int warp = tid >> 5, lane = tid & 31;
    const int gid = lane >> 2, t4 = lane & 3;
    const int warp_m = warp >> 1, warp_n = warp & 1;

    if (tid < 128) colacc[tid] = 0.0f;

    const unsigned* gB = g_k + ((size_t)b*TT + (size_t)j*128)*DD;
    const unsigned* qb = g_q + ((size_t)b*TT + (size_t)i0*128)*DD;   // tile t at +t*128*DD

    const uint32_t aoff = a_lane_off(warp_m, lane);
    const uint32_t boffB = base32 + b_lane_off<132>(warp_n, lane);

    // prologue: B tile + A chunk 0 (one group), then A chunk 1 (second group)
    {
        #pragma unroll
        for (int u = 0; u < 16; ++u) {
            int f = tid + u*256; int r = f >> 5; int c4 = (f & 31) * 4;
            cp16s(base32 + (unsigned)(r*132 + c4)*4, gB + (size_t)r*DD + c4);
        }
        #pragma unroll
        for (int u = 0; u < 4; ++u) {
            int f = tid + u*256; int r = f >> 3; int c4 = (f & 7) * 4;
            cp16s(aStage + (unsigned)(r*36 + c4)*4, qb + (size_t)r*DD + c4);
        }
        cp_commit();
    }

    auto loadA = [&](int g, int s) {
        int t = g >> 2, kc = g & 3;
        const unsigned* gA = qb + (size_t)t*128*DD + kc*32;
        uint32_t st = aStage + s*((unsigned)TILE_WORDS*4);
        #pragma unroll
        for (int u = 0; u < 4; ++u) {
            int f = tid + u*256; int r = f >> 3; int c4 = (f & 7) * 4;
            cp16s(st + (unsigned)(r*36 + c4)*4, gA + (size_t)r*DD + c4);
        }
        cp_commit();
    };

    float acc[2][8][4] = {};

    for (int g = 0; g < NCH; ++g) {
        asm volatile("cp.async.wait_group 0;\n" ::: "memory");
        __syncthreads();
        if (g + 1 < NCH) loadA(g + 1, (g + 1) & 1);

        const int kc = g & 3;
        uint32_t aB = aStage + (g & 1)*((unsigned)TILE_WORDS*4) + aoff;
        gemm_chunk<false, 132>(aB, boffB + kc*128, acc);

        if (kc == 3) {
            // epilogue for tile t = g>>2
            const int t = g >> 2;
            const int i = i0 + t;
            const bool diag = (i == j);
            unsigned* ptile = g_p + ((size_t)b*NPAIR + (size_t)i*(i+1)/2 + j) * (128*128);
            #pragma unroll
            for (int nt = 0; nt < 8; ++nt) {
                int colA = warp_n*64 + nt*8 + 2*t4;
                float sA = 0.0f, sB = 0.0f;
                #pragma unroll
                for (int mt = 0; mt < 2; ++mt) {
                    int r0 = warp_m*32 + mt*16 + gid;
                    float e0 = __expf(acc[mt][nt][0]*SCALE);
                    float e1 = __expf(acc[mt][nt][1]*SCALE);
                    float e2 = __expf(acc[mt][nt][2]*SCALE);
                    float e3 = __expf(acc[mt][nt][3]*SCALE);
                    if (diag) {
                        if (r0   < colA)   e0 = 0.0f;
                        if (r0   < colA+1) e1 = 0.0f;
                        if (r0+8 < colA)   e2 = 0.0f;
                        if (r0+8 < colA+1) e3 = 0.0f;
                    }
                    sA += e0 + e2;
                    sB += e1 + e3;
                    *(uint2*)&ptile[r0*128 + colA]     = make_uint2(pre_tf(e0), pre_tf(e1));
                    *(uint2*)&ptile[(r0+8)*128 + colA] = make_uint2(pre_tf(e2), pre_tf(e3));
                    acc[mt][nt][0] = 0.0f; acc[mt][nt][1] = 0.0f;
                    acc[mt][nt][2] = 0.0f; acc[mt][nt][3] = 0.0f;
                }
                // reduce over the 8 lanes (gid axis) sharing this column pair
                sA += __shfl_xor_sync(0xffffffffu, sA, 4);
                sA += __shfl_xor_sync(0xffffffffu, sA, 8);
                sA += __shfl_xor_sync(0xffffffffu, sA, 16);
                sB += __shfl_xor_sync(0xffffffffu, sB, 4);
                sB += __shfl_xor_sync(0xffffffffu, sB, 8);
                sB += __shfl_xor_sync(0xffffffffu, sB, 16);
                if (gid == 0) {
                    atomicAdd(&colacc[colA],   sA);
                    atomicAdd(&colacc[colA+1], sB);
                }
            }
        }
    }

    __syncthreads();
    if (tid < 128)
        atomicAdd(&g_colsum[(size_t)b*TT + (size_t)j*128 + tid], colacc[tid]);
}

// ---------------- kernel 3: V'^T[d][s] = V[s][d]/colsum[s], tf32, transposed ----------------
__global__ void vscale_t_kernel() {
    __shared__ float ts[32][33];
    const int s0 = blockIdx.x * 32, d0 = blockIdx.y * 32;
    const int tx = threadIdx.x, ty = threadIdx.y;
    #pragma unroll
    for (int q = 0; q < 4; ++q) {
        int s = s0 + ty + q*8;
        float r = 1.0f / g_colsum[s];
        ts[ty + q*8][tx] = g_v[(size_t)s*DD + d0 + tx] * r;
    }
    __syncthreads();
    #pragma unroll
    for (int q = 0; q < 4; ++q) {
        int d = d0 + ty + q*8;
        g_vpt[(size_t)d*M_TOTAL + s0 + tx] = pre_tf(ts[tx][ty + q*8]);
    }
}

// ---------------- kernel 4: pass 2 — out_i = sum_j P(i,j) @ V'(j) ----------------
__global__ __launch_bounds__(256, 2) void pass2_kernel(float* __restrict__ out)
{
    extern __shared__ unsigned sm[];
    const uint32_t base32 = (uint32_t)__cvta_generic_to_shared(sm);

    const int bx = blockIdx.x;
    int b, i, jlo, jhi;
    if (bx < 128)       { b = bx & 7;        i = 31 - (bx >> 3);        jlo = 0;  jhi = 16;    }
    else if (bx < 256)  { int t = bx - 128;  b = t & 7; i = 31 - (t >> 3); jlo = 16; jhi = i + 1; }
    else                { int t = bx - 256;  b = t & 7; i = 15 - (t >> 3); jlo = 0;  jhi = i + 1; }
    const int NC = (jhi - jlo) * 4;

    const int tid = threadIdx.x;
    const int warp = tid >> 5, lane = tid & 31;
    const int gid = lane >> 2, t4 = lane & 3;
    const int warp_m = warp >> 1, warp_n = warp & 1;

    const unsigned* pbase = g_p + ((size_t)b*NPAIR + (size_t)i*(i+1)/2) * (128*128);
    const unsigned* vbase = g_vpt + (size_t)b*TT;

    const uint32_t aoff = a_lane_off(warp_m, lane);
    const uint32_t boff = B_OFF_BYTES + b_lane_off<36>(warp_n, lane);

    auto loadc = [&](int cc, int s) {
        int j = jlo + (cc >> 2), kc = cc & 3;
        load_tiles(base32 + s*STAGE_BYTES, tid,
                   pbase + (size_t)j*(128*128) + kc*32, 128,
                   vbase + (size_t)j*128 + kc*32, (size_t)M_TOTAL);
    };

    float acc[2][8][4] = {};

    loadc(0, 0);
    loadc(1, 1);
    for (int c = 0; c < NC; ++c) {
        if (c + 1 < NC) asm volatile("cp.async.wait_group 1;\n" ::: "memory");
        else            asm volatile("cp.async.wait_group 0;\n" ::: "memory");
        __syncthreads();
        if (c + 2 < NC) loadc(c + 2, (c+2)%3);
        uint32_t st = base32 + (c%3)*STAGE_BYTES;
        gemm_chunk<false, 36>(st + aoff, st + boff, acc);
    }

    float* obase = out + ((size_t)b*TT + (size_t)i*128)*DD;
    const bool partial = (i >= 16);
    #pragma unroll
    for (int mt = 0; mt < 2; ++mt) {
        #pragma unroll
        for (int nt = 0; nt < 8; ++nt) {
            int r0 = warp_m*32 + mt*16 + gid;
            int col = warp_n*64 + nt*8 + 2*t4;
            float* p0 = &obase[(size_t)r0*DD + col];
            float* p1 = &obase[(size_t)(r0+8)*DD + col];
            if (partial) {
                atomicAdd(p0,   acc[mt][nt][0]);
                atomicAdd(p0+1, acc[mt][nt][1]);
                atomicAdd(p1,   acc[mt][nt][2]);
                atomicAdd(p1+1, acc[mt][nt][3]);
            } else {
                *(float2*)p0 = make_float2(acc[mt][nt][0], acc[mt][nt][1]);
                *(float2*)p1 = make_float2(acc[mt][nt][2], acc[mt][nt][3]);
            }
        }
    }
}

// ---------------- launch ----------------
extern "C" void kernel_launch(void* const* d_in, const int* in_sizes, int n_in,
                              void* d_out, int out_size)
{
    const float* x  = (const float*)d_in[0];
    const float* Wq = (const float*)d_in[1];
    const float* Wk = (const float*)d_in[2];
    const float* Wv = (const float*)d_in[3];
    float* out = (float*)d_out;

    cudaFuncSetAttribute(qkv_kernel,   cudaFuncAttributeMaxDynamicSharedMemorySize, GEMM_SMEM);
    cudaFuncSetAttribute(pass1_kernel, cudaFuncAttributeMaxDynamicSharedMemorySize, P1V2_SMEM);
    cudaFuncSetAttribute(pass2_kernel, cudaFuncAttributeMaxDynamicSharedMemorySize, GEMM_SMEM);

    zero_kernel<<<16384, 256>>>(out);
    wtrans_kernel<<<dim3(64, 3), 256>>>(Wq, Wk, Wv);
    qkv_kernel<<<768, 256, GEMM_SMEM>>>(x);
    pass1_kernel<<<dim3(144, BB), 256, P1V2_SMEM>>>();
    vscale_t_kernel<<<dim3(M_TOTAL/32, DD/32), dim3(32, 8)>>>();
    pass2_kernel<<<384, 256, GEMM_SMEM>>>(out);
}

// round 11
// speedup vs baseline: 1.4578x; 1.1883x over previous
#include <cuda_runtime.h>
#include <cuda_fp16.h>
#include <cstdint>

// Problem constants
#define BB 8
#define TT 4096
#define EE 2048
#define DD 128
#define M_TOTAL (BB*TT)            // 32768
#define NTILE 32
#define NPAIR 528                  // NTILE*(NTILE+1)/2
#define SCALE 0.08838834764831845f // 128^-0.5
#define OSCALE 0.00390625f         // 1/256 (undo V'' scaling)

// Scratch (static __device__ arrays: allocation-free per harness rules)
__device__ __half g_qh[M_TOTAL*DD];           // q, fp16 [t][d]
__device__ __half g_kh[M_TOTAL*DD];           // k, fp16 [s][d]
__device__ __half g_vh[M_TOTAL*DD];           // v, fp16 [s][d]
__device__ __half g_vpth[M_TOTAL*DD];         // V''^T = 256*V[s][d]/colsum[s], fp16 [d][s]
__device__ float  g_colsum[BB*TT];
__device__ __half g_ph[(size_t)BB*NPAIR*128*128];  // exp(score) tiles, fp16 (~138MB)
__device__ unsigned g_wt[3*DD*EE];            // W^T n-major [y][n][k], tf32 bits (3MB)

// ---------------- helpers ----------------
__device__ __forceinline__ unsigned pre_tf(float f) {
    return (__float_as_uint(f) + 0x1000u) & 0xFFFFE000u;
}
__device__ __forceinline__ unsigned fixtf(unsigned u) {
    return (u + 0x1000u) & 0xFFFFE000u;
}
__device__ __forceinline__ void cp16s(unsigned smem_dst, const void* gptr) {
    asm volatile("cp.async.cg.shared.global [%0], [%1], 16;\n" :: "r"(smem_dst), "l"(gptr));
}
__device__ __forceinline__ void cp_commit() {
    asm volatile("cp.async.commit_group;\n" ::: "memory");
}
__device__ __forceinline__ void mma_tf32(float c[4],
    unsigned a0, unsigned a1, unsigned a2, unsigned a3,
    unsigned b0, unsigned b1)
{
    asm volatile(
        "mma.sync.aligned.m16n8k8.row.col.f32.tf32.tf32.f32 "
        "{%0,%1,%2,%3}, {%4,%5,%6,%7}, {%8,%9}, {%0,%1,%2,%3};"
        : "+f"(c[0]), "+f"(c[1]), "+f"(c[2]), "+f"(c[3])
        : "r"(a0), "r"(a1), "r"(a2), "r"(a3), "r"(b0), "r"(b1));
}
__device__ __forceinline__ void mma_f16(float c[4],
    unsigned a0, unsigned a1, unsigned a2, unsigned a3,
    unsigned b0, unsigned b1)
{
    asm volatile(
        "mma.sync.aligned.m16n8k16.row.col.f32.f16.f16.f32 "
        "{%0,%1,%2,%3}, {%4,%5,%6,%7}, {%8,%9}, {%0,%1,%2,%3};"
        : "+f"(c[0]), "+f"(c[1]), "+f"(c[2]), "+f"(c[3])
        : "r"(a0), "r"(a1), "r"(a2), "r"(a3), "r"(b0), "r"(b1));
}
__device__ __forceinline__ void ldsm4(unsigned& r0, unsigned& r1, unsigned& r2, unsigned& r3,
                                      uint32_t addr) {
    asm volatile("ldmatrix.sync.aligned.m8n8.x4.shared.b16 {%0,%1,%2,%3}, [%4];"
        : "=r"(r0), "=r"(r1), "=r"(r2), "=r"(r3) : "r"(addr));
}

// ---- tf32 GEMM skeleton (qkv only): A[128][36]w + B[128][36]w per stage ----
#define TILE_WORDS 4608
#define B_OFF_BYTES 18432
#define STAGE_BYTES 36864
#define GEMM_SMEM (3*STAGE_BYTES)     // 110592

__device__ __forceinline__ void load_tiles(uint32_t st, int tid,
    const unsigned* gA, size_t sA, const unsigned* gB, size_t sB)
{
    #pragma unroll
    for (int u = 0; u < 4; ++u) {
        int f = tid + u*256; int r = f >> 3; int c4 = (f & 7) * 4;
        cp16s(st + (unsigned)(r*36 + c4)*4, gA + (size_t)r*sA + c4);
    }
    #pragma unroll
    for (int u = 0; u < 4; ++u) {
        int f = tid + u*256; int r = f >> 3; int c4 = (f & 7) * 4;
        cp16s(st + B_OFF_BYTES + (unsigned)(r*36 + c4)*4, gB + (size_t)r*sB + c4);
    }
    cp_commit();
}

template<bool FIX>
__device__ __forceinline__ void gemm_chunk(uint32_t a_base, uint32_t b_base,
                                           float (&acc)[2][8][4])
{
    #pragma unroll
    for (int kk = 0; kk < 4; ++kk) {
        unsigned a0[4], a1[4];
        ldsm4(a0[0], a0[1], a0[2], a0[3], a_base + kk*32);
        ldsm4(a1[0], a1[1], a1[2], a1[3], a_base + kk*32 + 2304);
        if (FIX) {
            #pragma unroll
            for (int q = 0; q < 4; ++q) { a0[q] = fixtf(a0[q]); a1[q] = fixtf(a1[q]); }
        }
        #pragma unroll
        for (int p = 0; p < 4; ++p) {
            unsigned b[4];
            ldsm4(b[0], b[1], b[2], b[3], b_base + kk*32 + p*2304);
            mma_tf32(acc[0][2*p],   a0[0], a0[1], a0[2], a0[3], b[0], b[1]);
            mma_tf32(acc[0][2*p+1], a0[0], a0[1], a0[2], a0[3], b[2], b[3]);
            mma_tf32(acc[1][2*p],   a1[0], a1[1], a1[2], a1[3], b[0], b[1]);
            mma_tf32(acc[1][2*p+1], a1[0], a1[1], a1[2], a1[3], b[2], b[3]);
        }
    }
}

__device__ __forceinline__ uint32_t a_lane_off(int warp_m, int lane) {
    int row = warp_m*32 + ((lane >> 3) & 1)*8 + (lane & 7);
    int col = (lane >> 4) * 4;
    return (uint32_t)(row*36 + col) * 4;
}
__device__ __forceinline__ uint32_t b_lane_off36(int warp_n, int lane) {
    int row = warp_n*64 + (lane >> 4)*8 + (lane & 7);
    int col = ((lane >> 3) & 1) * 4;
    return (uint32_t)(row*36 + col) * 4;
}

// ---- fp16 GEMM skeleton: tiles [128 rows][72 halves] (144B rows), k-chunk 64 ----
#define HSTAGE_BYTES 18432            // 128*144

// A fragment lane base: rows m (lane&15), k-halves (lane>>4)*8
__device__ __forceinline__ uint32_t ha_lane_off(int warp_m, int lane) {
    int row = warp_m*32 + (lane & 15);
    return (uint32_t)(row*144 + (lane >> 4)*16);
}
// B fragment lane base on [n][k] tile (no-trans ldmatrix)
template<int BSTRIDE_H>
__device__ __forceinline__ uint32_t hb_lane_off(int warp_n, int lane) {
    int row = warp_n*64 + ((lane >> 4) & 1)*8 + (lane & 7);
    return (uint32_t)(row*BSTRIDE_H*2 + ((lane >> 3) & 1)*16);
}

template<int BSTRIDE_H>
__device__ __forceinline__ void gemm_chunk_h(uint32_t a_base, uint32_t b_base,
                                             float (&acc)[2][8][4])
{
    const int PSTEP = 16*BSTRIDE_H*2;
    #pragma unroll
    for (int kk = 0; kk < 4; ++kk) {
        unsigned a0[4], a1[4];
        ldsm4(a0[0], a0[1], a0[2], a0[3], a_base + kk*32);
        ldsm4(a1[0], a1[1], a1[2], a1[3], a_base + kk*32 + 16*144);
        #pragma unroll
        for (int p = 0; p < 4; ++p) {
            unsigned b[4];
            ldsm4(b[0], b[1], b[2], b[3], b_base + kk*32 + p*PSTEP);
            mma_f16(acc[0][2*p],   a0[0], a0[1], a0[2], a0[3], b[0], b[1]);
            mma_f16(acc[0][2*p+1], a0[0], a0[1], a0[2], a0[3], b[2], b[3]);
            mma_f16(acc[1][2*p],   a1[0], a1[1], a1[2], a1[3], b[0], b[1]);
            mma_f16(acc[1][2*p+1], a1[0], a1[1], a1[2], a1[3], b[2], b[3]);
        }
    }
}

// ---------------- kernel 0: zero colsum and output ----------------
__global__ void zero_kernel(float* __restrict__ out) {
    int i = blockIdx.x * 256 + threadIdx.x;
    out[i] = 0.0f;
    if (i < BB*TT) g_colsum[i] = 0.0f;
}

// ---------------- kernel W: W^T n-major, tf32 pre-rounded ----------------
__global__ __launch_bounds__(256) void wtrans_kernel(
    const float* __restrict__ Wq, const float* __restrict__ Wk, const float* __restrict__ Wv)
{
    __shared__ float ws[32*129];
    const int kc = blockIdx.x, y = blockIdx.y;
    const float* W = (y == 0) ? Wq : (y == 1) ? Wk : Wv;
    const int tid = threadIdx.x;
    #pragma unroll
    for (int u = 0; u < 16; ++u) {
        int f = tid + u*256;
        int r = f >> 7, n = f & 127;
        ws[r*129 + n] = W[(size_t)(kc*32 + r)*DD + n];
    }
    __syncthreads();
    #pragma unroll
    for (int u = 0; u < 4; ++u) {
        int n = (tid >> 3) + u*32;
        int kq = (tid & 7) * 4;
        uint4 v;
        v.x = pre_tf(ws[(kq+0)*129 + n]);
        v.y = pre_tf(ws[(kq+1)*129 + n]);
        v.z = pre_tf(ws[(kq+2)*129 + n]);
        v.w = pre_tf(ws[(kq+3)*129 + n]);
        *(uint4*)&g_wt[((size_t)y*DD + n)*EE + kc*32 + kq] = v;
    }
}

// ---------------- kernel 1: QKV projection (tf32 mainloop, fp16 epilogue) ----------------
__global__ __launch_bounds__(256, 2) void qkv_kernel(const float* __restrict__ x)
{
    extern __shared__ unsigned sm[];
    const uint32_t base32 = (uint32_t)__cvta_generic_to_shared(sm);

    const int tid = threadIdx.x;
    const int warp = tid >> 5, lane = tid & 31;
    const int gid = lane >> 2, t4 = lane & 3;
    const int warp_m = warp >> 1, warp_n = warp & 1;
    const int bid = blockIdx.x;
    const int m0 = (bid / 3) * 128;
    const int y  = bid % 3;

    const unsigned* gA0 = (const unsigned*)x + (size_t)m0*EE;
    const unsigned* gB0 = g_wt + (size_t)y*DD*EE;

    const uint32_t aoff = a_lane_off(warp_m, lane);
    const uint32_t boff = B_OFF_BYTES + b_lane_off36(warp_n, lane);

    float acc[2][8][4] = {};

    load_tiles(base32,               tid, gA0,      EE, gB0,      EE);
    load_tiles(base32 + STAGE_BYTES, tid, gA0 + 32, EE, gB0 + 32, EE);

    for (int c = 0; c < 64; ++c) {
        if (c + 1 < 64) asm volatile("cp.async.wait_group 1;\n" ::: "memory");
        else            asm volatile("cp.async.wait_group 0;\n" ::: "memory");
        __syncthreads();
        if (c + 2 < 64)
            load_tiles(base32 + ((c+2)%3)*STAGE_BYTES, tid,
                       gA0 + (c+2)*32, EE, gB0 + (c+2)*32, EE);
        uint32_t st = base32 + (c%3)*STAGE_BYTES;
        gemm_chunk<true>(st + aoff, st + boff, acc);
    }

    #pragma unroll
    for (int mt = 0; mt < 2; ++mt) {
        #pragma unroll
        for (int nt = 0; nt < 8; ++nt) {
            int row = m0 + warp_m*32 + mt*16 + gid;
            int col = warp_n*64 + nt*8 + 2*t4;
            size_t o0 = (size_t)row*DD + col;
            size_t o1 = (size_t)(row+8)*DD + col;
            __half2 h0 = __floats2half2_rn(acc[mt][nt][0], acc[mt][nt][1]);
            __half2 h1 = __floats2half2_rn(acc[mt][nt][2], acc[mt][nt][3]);
            if (y == 0)      { *(__half2*)&g_qh[o0] = h0; *(__half2*)&g_qh[o1] = h1; }
            else if (y == 1) { *(__half2*)&g_kh[o0] = h0; *(__half2*)&g_kh[o1] = h1; }
            else             { *(__half2*)&g_vh[o0] = h0; *(__half2*)&g_vh[o1] = h1; }
        }
    }
}

// ---------------- kernel 2: pass 1 (fp16) — resident k-tile, streamed q-tiles ----------------
// grid (144, 8). smem: B[128][136]h (34816B) + A[2][128][72]h (36864B) = 71680B.
#define P1_BBYTES 34816
#define P1_SMEM   (P1_BBYTES + 2*HSTAGE_BYTES)
__global__ __launch_bounds__(256, 2) void pass1_kernel()
{
    extern __shared__ unsigned sm[];
    const uint32_t base32 = (uint32_t)__cvta_generic_to_shared(sm);
    const uint32_t aStage = base32 + P1_BBYTES;
    __shared__ float colacc[128];

    const int b = blockIdx.y;
    int rem = blockIdx.x, j = 0, mc = 0;
    #pragma unroll 1
    for (j = 0; j < 32; ++j) {
        int c = (32 - j + 3) >> 2;
        if (rem < c) { mc = rem; break; }
        rem -= c;
    }
    const int i0 = j + mc*4;
    const int ntl = (32 - i0 < 4) ? (32 - i0) : 4;
    const int NCH = ntl * 2;                     // k=64 chunks per 128-d tile: 2

    const int tid = threadIdx.x;
    const int warp = tid >> 5, lane = tid & 31;
    const int gid = lane >> 2, t4 = lane & 3;
    const int warp_m = warp >> 1, warp_n = warp & 1;

    if (tid < 128) colacc[tid] = 0.0f;

    const __half* gB = g_kh + ((size_t)b*TT + (size_t)j*128)*DD;
    const __half* qb = g_qh + ((size_t)b*TT + (size_t)i0*128)*DD;

    const uint32_t aoff  = ha_lane_off(warp_m, lane);
    const uint32_t boffB = base32 + hb_lane_off<136>(warp_n, lane);

    // prologue: resident B (128 rows x 256B) + A chunk 0
    {
        #pragma unroll
        for (int u = 0; u < 8; ++u) {
            int o = tid + u*256;                 // 0..2047
            int r = o >> 4, c = o & 15;
            cp16s(base32 + (unsigned)(r*272 + c*16), gB + (size_t)r*DD + c*8);
        }
        #pragma unroll
        for (int u = 0; u < 4; ++u) {
            int o = tid + u*256;                 // 0..1023
            int r = o >> 3, c = o & 7;
            cp16s(aStage + (unsigned)(r*144 + c*16), qb + (size_t)r*DD + c*8);
        }
        cp_commit();
    }

    auto loadA = [&](int g, int s) {
        int t = g >> 1, kc = g & 1;
        const __half* gA = qb + (size_t)t*128*DD + kc*64;
        uint32_t st = aStage + s*(unsigned)HSTAGE_BYTES;
        #pragma unroll
        for (int u = 0; u < 4; ++u) {
            int o = tid + u*256;
            int r = o >> 3, c = o & 7;
            cp16s(st + (unsigned)(r*144 + c*16), gA + (size_t)r*DD + c*8);
        }
        cp_commit();
    };

    float acc[2][8][4] = {};

    for (int g = 0; g < NCH; ++g) {
        asm volatile("cp.async.wait_group 0;\n" ::: "memory");
        __syncthreads();
        if (g + 1 < NCH) loadA(g + 1, (g + 1) & 1);

        const int kc = g & 1;
        uint32_t aB = aStage + (g & 1)*(unsigned)HSTAGE_BYTES + aoff;
        gemm_chunk_h<136>(aB, boffB + kc*128, acc);

        if (kc == 1) {
            const int t = g >> 1;
            const int i = i0 + t;
            const bool diag = (i == j);
            __half* ptile = g_ph + ((size_t)b*NPAIR + (size_t)i*(i+1)/2 + j) * (128*128);
            #pragma unroll
            for (int nt = 0; nt < 8; ++nt) {
                int colA = warp_n*64 + nt*8 + 2*t4;
                float sA = 0.0f, sB = 0.0f;
                #pragma unroll
                for (int mt = 0; mt < 2; ++mt) {
                    int r0 = warp_m*32 + mt*16 + gid;
                    float e0 = __expf(acc[mt][nt][0]*SCALE);
                    float e1 = __expf(acc[mt][nt][1]*SCALE);
                    float e2 = __expf(acc[mt][nt][2]*SCALE);
                    float e3 = __expf(acc[mt][nt][3]*SCALE);
                    if (diag) {
                        if (r0   < colA)   e0 = 0.0f;
                        if (r0   < colA+1) e1 = 0.0f;
                        if (r0+8 < colA)   e2 = 0.0f;
                        if (r0+8 < colA+1) e3 = 0.0f;
                    }
                    sA += e0 + e2;
                    sB += e1 + e3;
                    *(__half2*)&ptile[r0*128 + colA]     = __floats2half2_rn(e0, e1);
                    *(__half2*)&ptile[(r0+8)*128 + colA] = __floats2half2_rn(e2, e3);
                    acc[mt][nt][0] = 0.0f; acc[mt][nt][1] = 0.0f;
                    acc[mt][nt][2] = 0.0f; acc[mt][nt][3] = 0.0f;
                }
                sA += __shfl_xor_sync(0xffffffffu, sA, 4);
                sA += __shfl_xor_sync(0xffffffffu, sA, 8);
                sA += __shfl_xor_sync(0xffffffffu, sA, 16);
                sB += __shfl_xor_sync(0xffffffffu, sB, 4);
                sB += __shfl_xor_sync(0xffffffffu, sB, 8);
                sB += __shfl_xor_sync(0xffffffffu, sB, 16);
                if (gid == 0) {
                    atomicAdd(&colacc[colA],   sA);
                    atomicAdd(&colacc[colA+1], sB);
                }
            }
        }
    }

    __syncthreads();
    if (tid < 128)
        atomicAdd(&g_colsum[(size_t)b*TT + (size_t)j*128 + tid], colacc[tid]);
}

// ---------------- kernel 3: V''^T[d][s] = 256*V[s][d]/colsum[s], fp16, transposed ----------------
__global__ void vscale_t_kernel() {
    __shared__ float ts[32][33];
    const int s0 = blockIdx.x * 32, d0 = blockIdx.y * 32;
    const int tx = threadIdx.x, ty = threadIdx.y;
    #pragma unroll
    for (int q = 0; q < 4; ++q) {
        int s = s0 + ty + q*8;
        float r = 256.0f / g_colsum[s];
        ts[ty + q*8][tx] = __half2float(g_vh[(size_t)s*DD + d0 + tx]) * r;
    }
    __syncthreads();
    #pragma unroll
    for (int q = 0; q < 4; ++q) {
        int d = d0 + ty + q*8;
        g_vpth[(size_t)d*M_TOTAL + s0 + tx] = __float2half_rn(ts[tx][ty + q*8]);
    }
}

// ---------------- kernel 4: pass 2 (fp16) — out_i = (1/256) sum_j P(i,j) @ V''(j) ----------------
#define P2_STAGE (2*HSTAGE_BYTES)     // 36864
#define P2_SMEM  (3*P2_STAGE)         // 110592
__global__ __launch_bounds__(256, 2) void pass2_kernel(float* __restrict__ out)
{
    extern __shared__ unsigned sm[];
    const uint32_t base32 = (uint32_t)__cvta_generic_to_shared(sm);

    const int bx = blockIdx.x;
    int b, i, jlo, jhi;
    if (bx < 128)       { b = bx & 7;        i = 31 - (bx >> 3);        jlo = 0;  jhi = 16;    }
    else if (bx < 256)  { int t = bx - 128;  b = t & 7; i = 31 - (t >> 3); jlo = 16; jhi = i + 1; }
    else                { int t = bx - 256;  b = t & 7; i = 15 - (t >> 3); jlo = 0;  jhi = i + 1; }
    const int NC = (jhi - jlo) * 2;           // k=64 chunks

    const int tid = threadIdx.x;
    const int warp = tid >> 5, lane = tid & 31;
    const int gid = lane >> 2, t4 = lane & 3;
    const int warp_m = warp >> 1, warp_n = warp & 1;

    const __half* pbase = g_ph + ((size_t)b*NPAIR + (size_t)i*(i+1)/2) * (128*128);
    const __half* vbase = g_vpth + (size_t)b*TT;

    const uint32_t aoff = ha_lane_off(warp_m, lane);
    const uint32_t boff = HSTAGE_BYTES + hb_lane_off<72>(warp_n, lane);

    auto loadc = [&](int cc, int s) {
        int j = jlo + (cc >> 1), kc = cc & 1;
        const __half* pA = pbase + (size_t)j*(128*128) + kc*64;
        const __half* pB = vbase + (size_t)j*128 + kc*64;
        uint32_t st = base32 + s*(unsigned)P2_STAGE;
        #pragma unroll
        for (int u = 0; u < 4; ++u) {
            int o = tid + u*256;
            int r = o >> 3, c = o & 7;
            cp16s(st + (unsigned)(r*144 + c*16), pA + (size_t)r*128 + c*8);
        }
        #pragma unroll
        for (int u = 0; u < 4; ++u) {
            int o = tid + u*256;
            int r = o >> 3, c = o & 7;
            cp16s(st + (unsigned)HSTAGE_BYTES + (unsigned)(r*144 + c*16),
                  pB + (size_t)r*M_TOTAL + c*8);
        }
        cp_commit();
    };

    float acc[2][8][4] = {};

    loadc(0, 0);
    if (NC > 1) loadc(1, 1);
    for (int c = 0; c < NC; ++c) {
        if (c + 1 < NC) asm volatile("cp.async.wait_group 1;\n" ::: "memory");
        else            asm volatile("cp.async.wait_group 0;\n" ::: "memory");
        __syncthreads();
        if (c + 2 < NC) loadc(c + 2, (c+2)%3);
        uint32_t st = base32 + (c%3)*(unsigned)P2_STAGE;
        gemm_chunk_h<72>(st + aoff, st + boff, acc);
    }

    float* obase = out + ((size_t)b*TT + (size_t)i*128)*DD;
    const bool partial = (i >= 16);
    #pragma unroll
    for (int mt = 0; mt < 2; ++mt) {
        #pragma unroll
        for (int nt = 0; nt < 8; ++nt) {
            int r0 = warp_m*32 + mt*16 + gid;
            int col = warp_n*64 + nt*8 + 2*t4;
            float* p0 = &obase[(size_t)r0*DD + col];
            float* p1 = &obase[(size_t)(r0+8)*DD + col];
            float v0 = acc[mt][nt][0]*OSCALE, v1 = acc[mt][nt][1]*OSCALE;
            float v2 = acc[mt][nt][2]*OSCALE, v3 = acc[mt][nt][3]*OSCALE;
            if (partial) {
                atomicAdd(p0,   v0);
                atomicAdd(p0+1, v1);
                atomicAdd(p1,   v2);
                atomicAdd(p1+1, v3);
            } else {
                *(float2*)p0 = make_float2(v0, v1);
                *(float2*)p1 = make_float2(v2, v3);
            }
        }
    }
}

// ---------------- launch ----------------
extern "C" void kernel_launch(void* const* d_in, const int* in_sizes, int n_in,
                              void* d_out, int out_size)
{
    const float* x  = (const float*)d_in[0];
    const float* Wq = (const float*)d_in[1];
    const float* Wk = (const float*)d_in[2];
    const float* Wv = (const float*)d_in[3];
    float* out = (float*)d_out;

    cudaFuncSetAttribute(qkv_kernel,   cudaFuncAttributeMaxDynamicSharedMemorySize, GEMM_SMEM);
    cudaFuncSetAttribute(pass1_kernel, cudaFuncAttributeMaxDynamicSharedMemorySize, P1_SMEM);
    cudaFuncSetAttribute(pass2_kernel, cudaFuncAttributeMaxDynamicSharedMemorySize, P2_SMEM);

    zero_kernel<<<16384, 256>>>(out);
    wtrans_kernel<<<dim3(64, 3), 256>>>(Wq, Wk, Wv);
    qkv_kernel<<<768, 256, GEMM_SMEM>>>(x);
    pass1_kernel<<<dim3(144, BB), 256, P1_SMEM>>>();
    vscale_t_kernel<<<dim3(M_TOTAL/32, DD/32), dim3(32, 8)>>>();
    pass2_kernel<<<384, 256, P2_SMEM>>>(out);
}

// round 12
// speedup vs baseline: 1.8657x; 1.2799x over previous
#include <cuda_runtime.h>
#include <cuda_fp16.h>
#include <cstdint>

// Problem constants
#define BB 8
#define TT 4096
#define EE 2048
#define DD 128
#define M_TOTAL (BB*TT)            // 32768
#define NTILE 32
#define NPAIR 528                  // NTILE*(NTILE+1)/2
#define SCALE 0.08838834764831845f // 128^-0.5
#define OSCALE 0.00390625f         // 1/256 (undo V'' scaling)
#define WUNDO 0.015625f            // 1/64 (undo W scaling)

// Scratch (static __device__ arrays: allocation-free per harness rules)
__device__ __half g_xh[(size_t)M_TOTAL*EE];   // x, fp16 [t][e] (128MB)
__device__ __half g_qh[M_TOTAL*DD];           // q, fp16 [t][d]
__device__ __half g_kh[M_TOTAL*DD];           // k, fp16 [s][d]
__device__ __half g_vh[M_TOTAL*DD];           // v, fp16 [s][d]
__device__ __half g_vpth[M_TOTAL*DD];         // V''^T = 256*V[s][d]/colsum[s], fp16 [d][s]
__device__ float  g_colsum[BB*TT];
__device__ __half g_ph[(size_t)BB*NPAIR*128*128];  // exp(score) tiles, fp16 (~138MB)
__device__ __half g_wth[3*DD*EE];             // (64*W)^T n-major [y][n][k], fp16 (1.5MB)

// ---------------- helpers ----------------
__device__ __forceinline__ void cp16s(unsigned smem_dst, const void* gptr) {
    asm volatile("cp.async.cg.shared.global [%0], [%1], 16;\n" :: "r"(smem_dst), "l"(gptr));
}
__device__ __forceinline__ void cp_commit() {
    asm volatile("cp.async.commit_group;\n" ::: "memory");
}
__device__ __forceinline__ void mma_f16(float c[4],
    unsigned a0, unsigned a1, unsigned a2, unsigned a3,
    unsigned b0, unsigned b1)
{
    asm volatile(
        "mma.sync.aligned.m16n8k16.row.col.f32.f16.f16.f32 "
        "{%0,%1,%2,%3}, {%4,%5,%6,%7}, {%8,%9}, {%0,%1,%2,%3};"
        : "+f"(c[0]), "+f"(c[1]), "+f"(c[2]), "+f"(c[3])
        : "r"(a0), "r"(a1), "r"(a2), "r"(a3), "r"(b0), "r"(b1));
}
__device__ __forceinline__ void ldsm4(unsigned& r0, unsigned& r1, unsigned& r2, unsigned& r3,
                                      uint32_t addr) {
    asm volatile("ldmatrix.sync.aligned.m8n8.x4.shared.b16 {%0,%1,%2,%3}, [%4];"
        : "=r"(r0), "=r"(r1), "=r"(r2), "=r"(r3) : "r"(addr));
}
__device__ __forceinline__ unsigned h2u(__half2 h) {
    return *reinterpret_cast<unsigned*>(&h);
}

// ---- fp16 GEMM skeleton: tiles [128 rows][72 halves] (144B rows), k-chunk 64 ----
#define HSTAGE_BYTES 18432            // 128*144

// A fragment lane base: rows m (lane&15), k-halves (lane>>4)*8
__device__ __forceinline__ uint32_t ha_lane_off(int warp_m, int lane) {
    int row = warp_m*32 + (lane & 15);
    return (uint32_t)(row*144 + (lane >> 4)*16);
}
// B fragment lane base on [n][k] tile (no-trans ldmatrix)
template<int BSTRIDE_H>
__device__ __forceinline__ uint32_t hb_lane_off(int warp_n, int lane) {
    int row = warp_n*64 + ((lane >> 4) & 1)*8 + (lane & 7);
    return (uint32_t)(row*BSTRIDE_H*2 + ((lane >> 3) & 1)*16);
}

template<int BSTRIDE_H>
__device__ __forceinline__ void gemm_chunk_h(uint32_t a_base, uint32_t b_base,
                                             float (&acc)[2][8][4])
{
    const int PSTEP = 16*BSTRIDE_H*2;
    #pragma unroll
    for (int kk = 0; kk < 4; ++kk) {
        unsigned a0[4], a1[4];
        ldsm4(a0[0], a0[1], a0[2], a0[3], a_base + kk*32);
        ldsm4(a1[0], a1[1], a1[2], a1[3], a_base + kk*32 + 16*144);
        #pragma unroll
        for (int p = 0; p < 4; ++p) {
            unsigned b[4];
            ldsm4(b[0], b[1], b[2], b[3], b_base + kk*32 + p*PSTEP);
            mma_f16(acc[0][2*p],   a0[0], a0[1], a0[2], a0[3], b[0], b[1]);
            mma_f16(acc[0][2*p+1], a0[0], a0[1], a0[2], a0[3], b[2], b[3]);
            mma_f16(acc[1][2*p],   a1[0], a1[1], a1[2], a1[3], b[0], b[1]);
            mma_f16(acc[1][2*p+1], a1[0], a1[1], a1[2], a1[3], b[2], b[3]);
        }
    }
}

// ---------------- kernel 0: zero colsum and output ----------------
__global__ void zero_kernel(float* __restrict__ out) {
    int i = blockIdx.x * 256 + threadIdx.x;
    out[i] = 0.0f;
    if (i < BB*TT) g_colsum[i] = 0.0f;
}

// ---------------- kernel X: x fp32 -> fp16 ----------------
__global__ __launch_bounds__(256) void xconv_kernel(const float* __restrict__ x) {
    size_t base = ((size_t)blockIdx.x * 256 + threadIdx.x) * 8;
    float4 a = *(const float4*)(x + base);
    float4 b = *(const float4*)(x + base + 4);
    uint4 v;
    v.x = h2u(__floats2half2_rn(a.x, a.y));
    v.y = h2u(__floats2half2_rn(a.z, a.w));
    v.z = h2u(__floats2half2_rn(b.x, b.y));
    v.w = h2u(__floats2half2_rn(b.z, b.w));
    *(uint4*)&g_xh[base] = v;
}

// ---------------- kernel W: (64*W)^T n-major, fp16 ----------------
__global__ __launch_bounds__(256) void wtrans_kernel(
    const float* __restrict__ Wq, const float* __restrict__ Wk, const float* __restrict__ Wv)
{
    __shared__ float ws[32*129];
    const int kc = blockIdx.x, y = blockIdx.y;
    const float* W = (y == 0) ? Wq : (y == 1) ? Wk : Wv;
    const int tid = threadIdx.x;
    #pragma unroll
    for (int u = 0; u < 16; ++u) {
        int f = tid + u*256;
        int r = f >> 7, n = f & 127;
        ws[r*129 + n] = W[(size_t)(kc*32 + r)*DD + n];
    }
    __syncthreads();
    #pragma unroll
    for (int u = 0; u < 2; ++u) {
        int it = tid + u*256;              // 0..511
        int n = it >> 2, kq = (it & 3) * 8;
        uint4 v;
        v.x = h2u(__floats2half2_rn(64.0f*ws[(kq+0)*129 + n], 64.0f*ws[(kq+1)*129 + n]));
        v.y = h2u(__floats2half2_rn(64.0f*ws[(kq+2)*129 + n], 64.0f*ws[(kq+3)*129 + n]));
        v.z = h2u(__floats2half2_rn(64.0f*ws[(kq+4)*129 + n], 64.0f*ws[(kq+5)*129 + n]));
        v.w = h2u(__floats2half2_rn(64.0f*ws[(kq+6)*129 + n], 64.0f*ws[(kq+7)*129 + n]));
        *(uint4*)&g_wth[((size_t)y*DD + n)*EE + kc*32 + kq] = v;
    }
}

// ---------------- kernel 1: QKV projection (fp16) ----------------
// grid 768 (m-tile major, y fastest: siblings share x tile via L2).
#define QKV_STAGE (2*HSTAGE_BYTES)    // 36864
#define QKV_SMEM  (3*QKV_STAGE)       // 110592
__global__ __launch_bounds__(256, 2) void qkv_kernel()
{
    extern __shared__ unsigned sm[];
    const uint32_t base32 = (uint32_t)__cvta_generic_to_shared(sm);

    const int tid = threadIdx.x;
    const int warp = tid >> 5, lane = tid & 31;
    const int gid = lane >> 2, t4 = lane & 3;
    const int warp_m = warp >> 1, warp_n = warp & 1;
    const int bid = blockIdx.x;
    const int m0 = (bid / 3) * 128;
    const int y  = bid % 3;

    const __half* gA0 = g_xh + (size_t)m0*EE;
    const __half* gB0 = g_wth + (size_t)y*DD*EE;

    const uint32_t aoff = ha_lane_off(warp_m, lane);
    const uint32_t boff = HSTAGE_BYTES + hb_lane_off<72>(warp_n, lane);

    auto loadc = [&](int c, int s) {
        const __half* pA = gA0 + c*64;
        const __half* pB = gB0 + c*64;
        uint32_t st = base32 + s*(unsigned)QKV_STAGE;
        #pragma unroll
        for (int u = 0; u < 4; ++u) {
            int o = tid + u*256;
            int r = o >> 3, c8 = o & 7;
            cp16s(st + (unsigned)(r*144 + c8*16), pA + (size_t)r*EE + c8*8);
        }
        #pragma unroll
        for (int u = 0; u < 4; ++u) {
            int o = tid + u*256;
            int r = o >> 3, c8 = o & 7;
            cp16s(st + (unsigned)HSTAGE_BYTES + (unsigned)(r*144 + c8*16),
                  pB + (size_t)r*EE + c8*8);
        }
        cp_commit();
    };

    float acc[2][8][4] = {};

    loadc(0, 0);
    loadc(1, 1);
    for (int c = 0; c < 32; ++c) {
        if (c + 1 < 32) asm volatile("cp.async.wait_group 1;\n" ::: "memory");
        else            asm volatile("cp.async.wait_group 0;\n" ::: "memory");
        __syncthreads();
        if (c + 2 < 32) loadc(c + 2, (c+2)%3);
        uint32_t st = base32 + (c%3)*(unsigned)QKV_STAGE;
        gemm_chunk_h<72>(st + aoff, st + boff, acc);
    }

    #pragma unroll
    for (int mt = 0; mt < 2; ++mt) {
        #pragma unroll
        for (int nt = 0; nt < 8; ++nt) {
            int row = m0 + warp_m*32 + mt*16 + gid;
            int col = warp_n*64 + nt*8 + 2*t4;
            size_t o0 = (size_t)row*DD + col;
            size_t o1 = (size_t)(row+8)*DD + col;
            __half2 h0 = __floats2half2_rn(acc[mt][nt][0]*WUNDO, acc[mt][nt][1]*WUNDO);
            __half2 h1 = __floats2half2_rn(acc[mt][nt][2]*WUNDO, acc[mt][nt][3]*WUNDO);
            if (y == 0)      { *(__half2*)&g_qh[o0] = h0; *(__half2*)&g_qh[o1] = h1; }
            else if (y == 1) { *(__half2*)&g_kh[o0] = h0; *(__half2*)&g_kh[o1] = h1; }
            else             { *(__half2*)&g_vh[o0] = h0; *(__half2*)&g_vh[o1] = h1; }
        }
    }
}

// ---------------- kernel 2: pass 1 (fp16) — resident k-tile, streamed q-tiles ----------------
// grid (144, 8). smem: B[128][136]h (34816B) + A[2][128][72]h (36864B) = 71680B.
#define P1_BBYTES 34816
#define P1_SMEM   (P1_BBYTES + 2*HSTAGE_BYTES)
__global__ __launch_bounds__(256, 2) void pass1_kernel()
{
    extern __shared__ unsigned sm[];
    const uint32_t base32 = (uint32_t)__cvta_generic_to_shared(sm);
    const uint32_t aStage = base32 + P1_BBYTES;
    __shared__ float colacc[128];

    const int b = blockIdx.y;
    int rem = blockIdx.x, j = 0, mc = 0;
    #pragma unroll 1
    for (j = 0; j < 32; ++j) {
        int c = (32 - j + 3) >> 2;
        if (rem < c) { mc = rem; break; }
        rem -= c;
    }
    const int i0 = j + mc*4;
    const int ntl = (32 - i0 < 4) ? (32 - i0) : 4;
    const int NCH = ntl * 2;

    const int tid = threadIdx.x;
    const int warp = tid >> 5, lane = tid & 31;
    const int gid = lane >> 2, t4 = lane & 3;
    const int warp_m = warp >> 1, warp_n = warp & 1;

    if (tid < 128) colacc[tid] = 0.0f;

    const __half* gB = g_kh + ((size_t)b*TT + (size_t)j*128)*DD;
    const __half* qb = g_qh + ((size_t)b*TT + (size_t)i0*128)*DD;

    const uint32_t aoff  = ha_lane_off(warp_m, lane);
    const uint32_t boffB = base32 + hb_lane_off<136>(warp_n, lane);

    {
        #pragma unroll
        for (int u = 0; u < 8; ++u) {
            int o = tid + u*256;
            int r = o >> 4, c = o & 15;
            cp16s(base32 + (unsigned)(r*272 + c*16), gB + (size_t)r*DD + c*8);
        }
        #pragma unroll
        for (int u = 0; u < 4; ++u) {
            int o = tid + u*256;
            int r = o >> 3, c = o & 7;
            cp16s(aStage + (unsigned)(r*144 + c*16), qb + (size_t)r*DD + c*8);
        }
        cp_commit();
    }

    auto loadA = [&](int g, int s) {
        int t = g >> 1, kc = g & 1;
        const __half* gA = qb + (size_t)t*128*DD + kc*64;
        uint32_t st = aStage + s*(unsigned)HSTAGE_BYTES;
        #pragma unroll
        for (int u = 0; u < 4; ++u) {
            int o = tid + u*256;
            int r = o >> 3, c = o & 7;
            cp16s(st + (unsigned)(r*144 + c*16), gA + (size_t)r*DD + c*8);
        }
        cp_commit();
    };

    float acc[2][8][4] = {};

    for (int g = 0; g < NCH; ++g) {
        asm volatile("cp.async.wait_group 0;\n" ::: "memory");
        __syncthreads();
        if (g + 1 < NCH) loadA(g + 1, (g + 1) & 1);

        const int kc = g & 1;
        uint32_t aB = aStage + (g & 1)*(unsigned)HSTAGE_BYTES + aoff;
        gemm_chunk_h<136>(aB, boffB + kc*128, acc);

        if (kc == 1) {
            const int t = g >> 1;
            const int i = i0 + t;
            const bool diag = (i == j);
            __half* ptile = g_ph + ((size_t)b*NPAIR + (size_t)i*(i+1)/2 + j) * (128*128);
            #pragma unroll
            for (int nt = 0; nt < 8; ++nt) {
                int colA = warp_n*64 + nt*8 + 2*t4;
                float sA = 0.0f, sB = 0.0f;
                #pragma unroll
                for (int mt = 0; mt < 2; ++mt) {
                    int r0 = warp_m*32 + mt*16 + gid;
                    float e0 = __expf(acc[mt][nt][0]*SCALE);
                    float e1 = __expf(acc[mt][nt][1]*SCALE);
                    float e2 = __expf(acc[mt][nt][2]*SCALE);
                    float e3 = __expf(acc[mt][nt][3]*SCALE);
                    if (diag) {
                        if (r0   < colA)   e0 = 0.0f;
                        if (r0   < colA+1) e1 = 0.0f;
                        if (r0+8 < colA)   e2 = 0.0f;
                        if (r0+8 < colA+1) e3 = 0.0f;
                    }
                    sA += e0 + e2;
                    sB += e1 + e3;
                    *(__half2*)&ptile[r0*128 + colA]     = __floats2half2_rn(e0, e1);
                    *(__half2*)&ptile[(r0+8)*128 + colA] = __floats2half2_rn(e2, e3);
                    acc[mt][nt][0] = 0.0f; acc[mt][nt][1] = 0.0f;
                    acc[mt][nt][2] = 0.0f; acc[mt][nt][3] = 0.0f;
                }
                sA += __shfl_xor_sync(0xffffffffu, sA, 4);
                sA += __shfl_xor_sync(0xffffffffu, sA, 8);
                sA += __shfl_xor_sync(0xffffffffu, sA, 16);
                sB += __shfl_xor_sync(0xffffffffu, sB, 4);
                sB += __shfl_xor_sync(0xffffffffu, sB, 8);
                sB += __shfl_xor_sync(0xffffffffu, sB, 16);
                if (gid == 0) {
                    atomicAdd(&colacc[colA],   sA);
                    atomicAdd(&colacc[colA+1], sB);
                }
            }
        }
    }

    __syncthreads();
    if (tid < 128)
        atomicAdd(&g_colsum[(size_t)b*TT + (size_t)j*128 + tid], colacc[tid]);
}

// ---------------- kernel 3: V''^T[d][s] = 256*V[s][d]/colsum[s], fp16, transposed ----------------
__global__ void vscale_t_kernel() {
    __shared__ float ts[32][33];
    const int s0 = blockIdx.x * 32, d0 = blockIdx.y * 32;
    const int tx = threadIdx.x, ty = threadIdx.y;
    #pragma unroll
    for (int q = 0; q < 4; ++q) {
        int s = s0 + ty + q*8;
        float r = 256.0f / g_colsum[s];
        ts[ty + q*8][tx] = __half2float(g_vh[(size_t)s*DD + d0 + tx]) * r;
    }
    __syncthreads();
    #pragma unroll
    for (int q = 0; q < 4; ++q) {
        int d = d0 + ty + q*8;
        g_vpth[(size_t)d*M_TOTAL + s0 + tx] = __float2half_rn(ts[tx][ty + q*8]);
    }
}

// ---------------- kernel 4: pass 2 (fp16) — out_i = (1/256) sum_j P(i,j) @ V''(j) ----------------
#define P2_STAGE (2*HSTAGE_BYTES)
#define P2_SMEM  (3*P2_STAGE)
__global__ __launch_bounds__(256, 2) void pass2_kernel(float* __restrict__ out)
{
    extern __shared__ unsigned sm[];
    const uint32_t base32 = (uint32_t)__cvta_generic_to_shared(sm);

    const int bx = blockIdx.x;
    int b, i, jlo, jhi;
    if (bx < 128)       { b = bx & 7;        i = 31 - (bx >> 3);        jlo = 0;  jhi = 16;    }
    else if (bx < 256)  { int t = bx - 128;  b = t & 7; i = 31 - (t >> 3); jlo = 16; jhi = i + 1; }
    else                { int t = bx - 256;  b = t & 7; i = 15 - (t >> 3); jlo = 0;  jhi = i + 1; }
    const int NC = (jhi - jlo) * 2;

    const int tid = threadIdx.x;
    const int warp = tid >> 5, lane = tid & 31;
    const int gid = lane >> 2, t4 = lane & 3;
    const int warp_m = warp >> 1, warp_n = warp & 1;

    const __half* pbase = g_ph + ((size_t)b*NPAIR + (size_t)i*(i+1)/2) * (128*128);
    const __half* vbase = g_vpth + (size_t)b*TT;

    const uint32_t aoff = ha_lane_off(warp_m, lane);
    const uint32_t boff = HSTAGE_BYTES + hb_lane_off<72>(warp_n, lane);

    auto loadc = [&](int cc, int s) {
        int j = jlo + (cc >> 1), kc = cc & 1;
        const __half* pA = pbase + (size_t)j*(128*128) + kc*64;
        const __half* pB = vbase + (size_t)j*128 + kc*64;
        uint32_t st = base32 + s*(unsigned)P2_STAGE;
        #pragma unroll
        for (int u = 0; u < 4; ++u) {
            int o = tid + u*256;
            int r = o >> 3, c = o & 7;
            cp16s(st + (unsigned)(r*144 + c*16), pA + (size_t)r*128 + c*8);
        }
        #pragma unroll
        for (int u = 0; u < 4; ++u) {
            int o = tid + u*256;
            int r = o >> 3, c = o & 7;
            cp16s(st + (unsigned)HSTAGE_BYTES + (unsigned)(r*144 + c*16),
                  pB + (size_t)r*M_TOTAL + c*8);
        }
        cp_commit();
    };

    float acc[2][8][4] = {};

    loadc(0, 0);
    if (NC > 1) loadc(1, 1);
    for (int c = 0; c < NC; ++c) {
        if (c + 1 < NC) asm volatile("cp.async.wait_group 1;\n" ::: "memory");
        else            asm volatile("cp.async.wait_group 0;\n" ::: "memory");
        __syncthreads();
        if (c + 2 < NC) loadc(c + 2, (c+2)%3);
        uint32_t st = base32 + (c%3)*(unsigned)P2_STAGE;
        gemm_chunk_h<72>(st + aoff, st + boff, acc);
    }

    float* obase = out + ((size_t)b*TT + (size_t)i*128)*DD;
    const bool partial = (i >= 16);
    #pragma unroll
    for (int mt = 0; mt < 2; ++mt) {
        #pragma unroll
        for (int nt = 0; nt < 8; ++nt) {
            int r0 = warp_m*32 + mt*16 + gid;
            int col = warp_n*64 + nt*8 + 2*t4;
            float* p0 = &obase[(size_t)r0*DD + col];
            float* p1 = &obase[(size_t)(r0+8)*DD + col];
            float v0 = acc[mt][nt][0]*OSCALE, v1 = acc[mt][nt][1]*OSCALE;
            float v2 = acc[mt][nt][2]*OSCALE, v3 = acc[mt][nt][3]*OSCALE;
            if (partial) {
                atomicAdd(p0,   v0);
                atomicAdd(p0+1, v1);
                atomicAdd(p1,   v2);
                atomicAdd(p1+1, v3);
            } else {
                *(float2*)p0 = make_float2(v0, v1);
                *(float2*)p1 = make_float2(v2, v3);
            }
        }
    }
}

// ---------------- launch ----------------
extern "C" void kernel_launch(void* const* d_in, const int* in_sizes, int n_in,
                              void* d_out, int out_size)
{
    const float* x  = (const float*)d_in[0];
    const float* Wq = (const float*)d_in[1];
    const float* Wk = (const float*)d_in[2];
    const float* Wv = (const float*)d_in[3];
    float* out = (float*)d_out;

    cudaFuncSetAttribute(qkv_kernel,   cudaFuncAttributeMaxDynamicSharedMemorySize, QKV_SMEM);
    cudaFuncSetAttribute(pass1_kernel, cudaFuncAttributeMaxDynamicSharedMemorySize, P1_SMEM);
    cudaFuncSetAttribute(pass2_kernel, cudaFuncAttributeMaxDynamicSharedMemorySize, P2_SMEM);

    zero_kernel<<<16384, 256>>>(out);
    xconv_kernel<<<32768, 256>>>(x);
    wtrans_kernel<<<dim3(64, 3), 256>>>(Wq, Wk, Wv);
    qkv_kernel<<<768, 256, QKV_SMEM>>>();
    pass1_kernel<<<dim3(144, BB), 256, P1_SMEM>>>();
    vscale_t_kernel<<<dim3(M_TOTAL/32, DD/32), dim3(32, 8)>>>();
    pass2_kernel<<<384, 256, P2_SMEM>>>(out);
}